// round 8
// baseline (speedup 1.0000x reference)
#include <cuda_runtime.h>
#include <cuda_bf16.h>
#include <math.h>
#include <stdint.h>

#define T_  256
#define B_  64
#define D_  1024
#define H_  1024
#define DH_ 2048
#define NG_ 4096   /* 4 gates * H, packed n = j*4 + gate */
#define BH_ (B_ * H_)
#define M_  (T_ * B_)   /* 16384 */

// ---------------------------------------------------------------------------
// Device globals (scratch; no runtime allocation allowed)
// ---------------------------------------------------------------------------
// Zx in per-CTA slabs: [t][grp=0..127][64 b x 32 cols] fp32, slab = 8KB contiguous
__device__ float g_zx[(size_t)T_ * B_ * NG_];
__device__ __nv_bfloat16 g_whh[(size_t)NG_ * H_];      // packed Wh hi
__device__ __nv_bfloat16 g_whl[(size_t)NG_ * H_];      // packed Wh lo
__device__ __nv_bfloat16 g_wxh[(size_t)NG_ * D_];      // packed Wx hi
__device__ __nv_bfloat16 g_wxl[(size_t)NG_ * D_];      // packed Wx lo
__device__ __nv_bfloat16 g_xh[(size_t)M_ * D_];        // X hi
__device__ __nv_bfloat16 g_xl[(size_t)M_ * D_];        // X lo
// h double buffer, pre-swizzled chunk-major: [buf][hi/lo][c64 0..15][8192 B]
__device__ __align__(128) char g_hsw[2][2][16][8192];
__device__ unsigned g_cnt[16];                         // per-chunk dataflow counters

#define HBUF_STRIDE_ 262144   /* 2*16*8192 */
#define HHALF_STRIDE_ 131072  /* 16*8192 */

// ---------------------------------------------------------------------------
// PTX helpers (compute_103-portable)
// ---------------------------------------------------------------------------
__device__ __forceinline__ uint32_t smem_u32(const void* p) {
    uint32_t a;
    asm("{ .reg .u64 t; cvta.to.shared.u64 t, %1; cvt.u32.u64 %0, t; }" : "=r"(a) : "l"(p));
    return a;
}
__device__ __forceinline__ void cp_async16(uint32_t smem, const void* g) {
    asm volatile("cp.async.cg.shared.global [%0], [%1], 16;" :: "r"(smem), "l"(g) : "memory");
}
#define CP_COMMIT() asm volatile("cp.async.commit_group;" ::: "memory")
#define CP_WAIT(n)  asm volatile("cp.async.wait_group %0;" :: "n"(n) : "memory")

// 1D bulk copy global->shared with mbarrier completion (sm_90+, portable)
__device__ __forceinline__ void cp_bulk(uint32_t dst, const void* src, uint32_t bytes,
                                        uint32_t mbar) {
    asm volatile("cp.async.bulk.shared::cta.global.mbarrier::complete_tx::bytes "
                 "[%0], [%1], %2, [%3];"
                 :: "r"(dst), "l"(src), "r"(bytes), "r"(mbar) : "memory");
}
#define MBARRIER_INIT(mbar, cnt) \
    asm volatile("mbarrier.init.shared.b64 [%0], %1;" :: "r"((uint32_t)(mbar)), "r"((uint32_t)(cnt)) : "memory")
#define MBARRIER_EXPECT_TX(mbar, bytes) \
    asm volatile("mbarrier.arrive.expect_tx.shared.b64 _, [%0], %1;" \
        :: "r"((uint32_t)(mbar)), "r"((uint32_t)(bytes)) : "memory")
#define MBARRIER_WAIT_PARITY(mbar, parity) do { \
    uint32_t _m = (uint32_t)(mbar); uint32_t _p = (uint32_t)(parity); uint32_t _d; \
    asm volatile("{\n\t.reg .pred p;\n\t" \
        "mbarrier.try_wait.parity.acquire.cta.shared::cta.b64 p, [%1], %2;\n\t" \
        "selp.b32 %0, 1, 0, p;\n\t}" : "=r"(_d) : "r"(_m), "r"(_p) : "memory"); \
    if (!_d) { \
        asm volatile("{\n\t.reg .pred P1;\n\tWL_%=:\n\t" \
            "mbarrier.try_wait.parity.acquire.cta.shared::cta.b64 P1, [%0], %1, 0x989680;\n\t" \
            "@P1 bra.uni WD_%=;\n\tbra.uni WL_%=;\n\tWD_%=:\n\t}" \
            :: "r"(_m), "r"(_p) : "memory"); \
    } } while (0)

__device__ __forceinline__ void ldsm_x4(uint32_t& r0, uint32_t& r1, uint32_t& r2, uint32_t& r3,
                                        uint32_t addr) {
    asm volatile("ldmatrix.sync.aligned.m8n8.x4.shared.b16 {%0,%1,%2,%3}, [%4];"
                 : "=r"(r0), "=r"(r1), "=r"(r2), "=r"(r3) : "r"(addr));
}
__device__ __forceinline__ void mma_bf16(float* c,
                                         uint32_t a0, uint32_t a1, uint32_t a2, uint32_t a3,
                                         uint32_t b0, uint32_t b1) {
    asm volatile("mma.sync.aligned.m16n8k16.row.col.f32.bf16.bf16.f32 "
                 "{%0,%1,%2,%3}, {%4,%5,%6,%7}, {%8,%9}, {%0,%1,%2,%3};"
                 : "+f"(c[0]), "+f"(c[1]), "+f"(c[2]), "+f"(c[3])
                 : "r"(a0), "r"(a1), "r"(a2), "r"(a3), "r"(b0), "r"(b1));
}
#define SWZ(off) ((off) ^ (((off) >> 3) & 0x70))

__device__ __forceinline__ float sigf(float x) { return 1.0f / (1.0f + __expf(-x)); }
__device__ __forceinline__ float tanh_fast(float x) {
    float a = fabsf(x);
    float e = __expf(-2.0f * a);
    float t = (1.0f - e) / (1.0f + e);
    return copysignf(t, x);
}

// ---------------------------------------------------------------------------
// Phase 0a: split Wh (h-part) into packed bf16 hi/lo. Row n=(j<<2)|gate.
// ---------------------------------------------------------------------------
__global__ __launch_bounds__(256) void conv_w(
    const float* __restrict__ Wf, const float* __restrict__ Wi,
    const float* __restrict__ Wu, const float* __restrict__ Wo,
    __nv_bfloat16* __restrict__ hi, __nv_bfloat16* __restrict__ lo)
{
    size_t idx = (size_t)blockIdx.x * 256 + threadIdx.x;   // over NG_*H_
    int n = (int)(idx >> 10);
    int k = (int)(idx & 1023);
    int j = n >> 2, gate = n & 3;
    const float* W = (gate == 0) ? Wf : (gate == 1) ? Wi : (gate == 2) ? Wu : Wo;
    float w = W[(size_t)j * DH_ + D_ + k];
    __nv_bfloat16 h16 = __float2bfloat16(w);
    hi[idx] = h16;
    lo[idx] = __float2bfloat16(w - __bfloat162float(h16));
}

// Phase 0b: split Wx (x-part) into packed bf16 hi/lo. Row n=(j<<2)|gate.
__global__ __launch_bounds__(256) void conv_wx(
    const float* __restrict__ Wf, const float* __restrict__ Wi,
    const float* __restrict__ Wu, const float* __restrict__ Wo,
    __nv_bfloat16* __restrict__ hi, __nv_bfloat16* __restrict__ lo)
{
    size_t idx = (size_t)blockIdx.x * 256 + threadIdx.x;   // over NG_*D_
    int n = (int)(idx >> 10);
    int k = (int)(idx & 1023);
    int j = n >> 2, gate = n & 3;
    const float* W = (gate == 0) ? Wf : (gate == 1) ? Wi : (gate == 2) ? Wu : Wo;
    float w = W[(size_t)j * DH_ + k];
    __nv_bfloat16 h16 = __float2bfloat16(w);
    hi[idx] = h16;
    lo[idx] = __float2bfloat16(w - __bfloat162float(h16));
}

// Phase 0c: split X into bf16 hi/lo.
__global__ __launch_bounds__(256) void conv_x(
    const float* __restrict__ X,
    __nv_bfloat16* __restrict__ hi, __nv_bfloat16* __restrict__ lo)
{
    size_t idx = (size_t)blockIdx.x * 256 + threadIdx.x;   // over M_*D_
    float x = X[idx];
    __nv_bfloat16 h16 = __float2bfloat16(x);
    hi[idx] = h16;
    lo[idx] = __float2bfloat16(x - __bfloat162float(h16));
}

// ---------------------------------------------------------------------------
// Phase 1: input projection on tensor cores (split bf16). Unchanged from R7.
// Z written in per-CTA slab layout: zidx(m,n) =
//   ((m>>6)*128 + (n>>5))*2048 + (m&63)*32 + (n&31)
// ---------------------------------------------------------------------------
#define GS_(s)   ((s) * 65536)
#define GA_HI(s) (GS_(s) + 0)
#define GA_LO(s) (GS_(s) + 16384)
#define GB_HI(s) (GS_(s) + 32768)
#define GB_LO(s) (GS_(s) + 49152)
#define GSMEM_   131072

__global__ __launch_bounds__(256) void gemm_tc(
    const __nv_bfloat16* __restrict__ Xh, const __nv_bfloat16* __restrict__ Xl,
    const __nv_bfloat16* __restrict__ Wxh, const __nv_bfloat16* __restrict__ Wxl,
    const float* __restrict__ bf, const float* __restrict__ bi,
    const float* __restrict__ bu, const float* __restrict__ bo,
    float* __restrict__ Z)
{
    extern __shared__ __align__(1024) char sm[];
    __shared__ float s_bias[128];

    const uint32_t sbase = smem_u32(sm);
    const int tid  = threadIdx.x;
    const int wid  = tid >> 5;
    const int lane = tid & 31;
    const int n0   = blockIdx.x * 128;   // packed col base
    const int m0   = blockIdx.y * 128;

    const int wm = wid & 1;              // M half (64 rows)
    const int wn = wid >> 1;             // N quarter (32 cols)

    if (tid < 128) {
        int n = n0 + tid, gate = n & 3, j = n >> 2;
        const float* Ba = (gate == 0) ? bf : (gate == 1) ? bi : (gate == 2) ? bu : bo;
        s_bias[tid] = Ba[j];
    }

    const char* xh8 = (const char*)(Xh + (size_t)m0 * D_);
    const char* xl8 = (const char*)(Xl + (size_t)m0 * D_);
    const char* wh8 = (const char*)(Wxh + (size_t)n0 * D_);
    const char* wl8 = (const char*)(Wxl + (size_t)n0 * D_);

    auto load_chunk = [&](int ch, int s) {
#pragma unroll
        for (int r4 = 0; r4 < 4; r4++) {
            int idx = tid + r4 * 256;
            int row = idx >> 3, cg = idx & 7;
            size_t goff = (size_t)row * 2048 + (size_t)ch * 128 + cg * 16;
            uint32_t soff = SWZ((uint32_t)(row * 128 + cg * 16));
            cp_async16(sbase + GA_HI(s) + soff, xh8 + goff);
            cp_async16(sbase + GA_LO(s) + soff, xl8 + goff);
            cp_async16(sbase + GB_HI(s) + soff, wh8 + goff);
            cp_async16(sbase + GB_LO(s) + soff, wl8 + goff);
        }
    };

    float acc[4][4][4];
#pragma unroll
    for (int mt = 0; mt < 4; mt++)
#pragma unroll
        for (int nt = 0; nt < 4; nt++)
#pragma unroll
            for (int i = 0; i < 4; i++) acc[mt][nt][i] = 0.0f;

    const uint32_t a_kb = (uint32_t)((lane >> 4) << 3);
    const uint32_t b_nt = (uint32_t)((lane >> 3) >> 1);
    const uint32_t b_kb = (uint32_t)(((lane >> 3) & 1) * 8);
    const uint32_t b_r  = (uint32_t)(lane & 7);

    load_chunk(0, 0);
    CP_COMMIT();

    for (int ch = 0; ch < 16; ch++) {
        const int s = ch & 1;
        if (ch + 1 < 16) {
            load_chunk(ch + 1, s ^ 1);
            CP_COMMIT();
            CP_WAIT(1);
        } else {
            CP_WAIT(0);
        }
        __syncthreads();

        const uint32_t Ah = sbase + GA_HI(s), Al = sbase + GA_LO(s);
        const uint32_t Bh = sbase + GB_HI(s), Bl = sbase + GB_LO(s);

#pragma unroll
        for (int ks = 0; ks < 4; ks++) {
            uint32_t ah[4][4], al[4][4];
#pragma unroll
            for (int mt = 0; mt < 4; mt++) {
                uint32_t row = (uint32_t)(wm * 64 + mt * 16 + (lane & 15));
                uint32_t aoff = SWZ((row << 7) + (ks * 16 + a_kb) * 2);
                ldsm_x4(ah[mt][0], ah[mt][1], ah[mt][2], ah[mt][3], Ah + aoff);
                ldsm_x4(al[mt][0], al[mt][1], al[mt][2], al[mt][3], Al + aoff);
            }
            uint32_t bh[8], bl[8];
#pragma unroll
            for (int np = 0; np < 2; np++) {
                uint32_t row = (uint32_t)(wn * 32) + (np * 2 + b_nt) * 8 + b_r;
                uint32_t boff = SWZ((row << 7) + (ks * 16 + b_kb) * 2);
                ldsm_x4(bh[np*4+0], bh[np*4+1], bh[np*4+2], bh[np*4+3], Bh + boff);
                ldsm_x4(bl[np*4+0], bl[np*4+1], bl[np*4+2], bl[np*4+3], Bl + boff);
            }
#pragma unroll
            for (int mt = 0; mt < 4; mt++)
#pragma unroll
                for (int nt = 0; nt < 4; nt++) {
                    mma_bf16(acc[mt][nt], ah[mt][0], ah[mt][1], ah[mt][2], ah[mt][3],
                             bh[nt*2], bh[nt*2+1]);
                    mma_bf16(acc[mt][nt], ah[mt][0], ah[mt][1], ah[mt][2], ah[mt][3],
                             bl[nt*2], bl[nt*2+1]);
                    mma_bf16(acc[mt][nt], al[mt][0], al[mt][1], al[mt][2], al[mt][3],
                             bh[nt*2], bh[nt*2+1]);
                }
        }
        __syncthreads();
    }

    const int g  = lane >> 2;
    const int tg = lane & 3;
#pragma unroll
    for (int mt = 0; mt < 4; mt++) {
        int r0 = m0 + wm * 64 + mt * 16 + g;
#pragma unroll
        for (int nt = 0; nt < 4; nt++) {
            int nl = wn * 32 + nt * 8 + tg * 2;
            int n  = n0 + nl;
            float bia0 = s_bias[nl], bia1 = s_bias[nl + 1];
            float2 v0 = make_float2(acc[mt][nt][0] + bia0, acc[mt][nt][1] + bia1);
            float2 v1 = make_float2(acc[mt][nt][2] + bia0, acc[mt][nt][3] + bia1);
            size_t z0 = ((size_t)(r0 >> 6) * 128 + (n >> 5)) * 2048 + (r0 & 63) * 32 + (n & 31);
            int r1 = r0 + 8;
            size_t z1 = ((size_t)(r1 >> 6) * 128 + (n >> 5)) * 2048 + (r1 & 63) * 32 + (n & 31);
            *(float2*)&Z[z0] = v0;
            *(float2*)&Z[z1] = v1;
        }
    }
}

// ---------------------------------------------------------------------------
// Phase 2: persistent recurrence v4 — per-chunk dataflow flags (no grid barrier).
// h chunk c64 is produced by CTAs [c64*8, c64*8+8); counter g_cnt[c64] is
// bumped (release) by each after its epilogue. Copy issue polls (acquire)
// cnt >= 8*t before fetching that chunk, overlapping waits with compute.
// ---------------------------------------------------------------------------
#define W_HI_     0
#define W_LO_     65536
#define AST_(s)   (131072 + (s) * 32768)
#define ZX_OFF_   196608
#define ZS_OFF_   131072
#define SMEM_DYN_ 204800

__global__ __launch_bounds__(256) void lstm_persist(
    const float* __restrict__ Zx_all,
    const __nv_bfloat16* __restrict__ Whh,
    const __nv_bfloat16* __restrict__ Whl,
    char* __restrict__ Hsw,            // g_hsw base
    unsigned* __restrict__ cnt,        // g_cnt[16]
    const float* __restrict__ gbf, const float* __restrict__ gbi,
    const float* __restrict__ gbu, const float* __restrict__ gbo,
    float* __restrict__ out,           // [T][B][H]
    float* __restrict__ hc_tail)       // null or [hx|cx]
{
    extern __shared__ __align__(1024) char sm[];
    __shared__ float s_gb[32];
    __shared__ __align__(8) uint64_t s_mbar[3];   // stage0, stage1, zx

    const uint32_t sbase = smem_u32(sm);
    const int tid  = threadIdx.x;
    const int wid  = tid >> 5;
    const int lane = tid & 31;
    const int bx   = blockIdx.x;
    const int j0   = bx * 8;

    if (tid < 32) {
        int gate = tid >> 3, jl = tid & 7;
        const float* gp = (gate == 0) ? gbf : (gate == 1) ? gbi : (gate == 2) ? gbu : gbo;
        s_gb[tid] = gp[j0 + jl];
    }
    if (tid == 0) {
        MBARRIER_INIT(smem_u32(&s_mbar[0]), 1);
        MBARRIER_INIT(smem_u32(&s_mbar[1]), 1);
        MBARRIER_INIT(smem_u32(&s_mbar[2]), 1);
    }

    // ---- resident weights once ----
    {
        const char* wh8 = (const char*)(Whh + (size_t)bx * 32 * H_);
        const char* wl8 = (const char*)(Whl + (size_t)bx * 32 * H_);
        for (int i = tid; i < 4096; i += 256) {
            int c  = i >> 8;
            int r  = (i >> 3) & 31;
            int cg = i & 7;
            size_t goff = (size_t)r * 2048 + (size_t)c * 128 + cg * 16;
            uint32_t soff = (uint32_t)c * 4096 + SWZ((uint32_t)(r * 128 + cg * 16));
            cp_async16(sbase + W_HI_ + soff, wh8 + goff);
            cp_async16(sbase + W_LO_ + soff, wl8 + goff);
        }
        CP_COMMIT(); CP_WAIT(0);
        __syncthreads();
    }

    const int wm = wid & 3;
    const int wn = wid >> 2;
    const int m0 = wm * 16;

    const uint32_t a_r  = (uint32_t)(m0 + (lane & 15));
    const uint32_t a_kb = (uint32_t)((lane >> 4) << 3);
    const uint32_t b_nt = (uint32_t)((lane >> 3) >> 1);
    const uint32_t b_kb = (uint32_t)(((lane >> 3) & 1) * 8);
    const uint32_t b_r  = (uint32_t)(lane & 7);
    const uint32_t b_row = (uint32_t)(wn * 16) + b_nt * 8 + b_r;

    const uint32_t mb0 = smem_u32(&s_mbar[0]);
    const uint32_t mb1 = smem_u32(&s_mbar[1]);
    const uint32_t mbz = smem_u32(&s_mbar[2]);

    int ph[2] = {0, 0};
    int phz = 0;

    float c_reg[2] = {0.f, 0.f};

    const int hc64 = j0 >> 6;          // this CTA's produced h chunk
    const int kcb  = j0 & 63;

    // poll a chunk's readiness (tid 0 only)
    auto wait_c64 = [&](int c64, unsigned tgt) {
        if (!tgt) return;
        unsigned v;
        do {
            asm volatile("ld.acquire.gpu.u32 %0, [%1];" : "=r"(v) : "l"(cnt + c64) : "memory");
        } while (v < tgt);
    };
    // issue 128-col chunk pc of hin into stage s (tid 0 only)
    auto issue_chunk = [&](const char* hin, int pc, int s, unsigned tgt) {
        wait_c64(2 * pc, tgt);
        wait_c64(2 * pc + 1, tgt);
        asm volatile("fence.proxy.async;" ::: "memory");
        uint32_t mb = s ? mb1 : mb0;
        MBARRIER_EXPECT_TX(mb, 32768);
#pragma unroll
        for (int sub = 0; sub < 2; sub++) {
            int c64 = pc * 2 + sub;
            cp_bulk(sbase + AST_(s) + sub * 8192,
                    hin + (size_t)c64 * 8192, 8192, mb);
            cp_bulk(sbase + AST_(s) + 16384 + sub * 8192,
                    hin + HHALF_STRIDE_ + (size_t)c64 * 8192, 8192, mb);
        }
    };

    for (int t = 0; t < T_; t++) {
        const char* hin = Hsw + (size_t)(t & 1) * HBUF_STRIDE_;
        char* hout = Hsw + (size_t)((t + 1) & 1) * HBUF_STRIDE_;
        const unsigned tgt = (unsigned)(8 * t);

        // issue step's ZX slab + first two chunks (tid 0)
        if (tid == 0) {
            asm volatile("fence.proxy.async;" ::: "memory");
            MBARRIER_EXPECT_TX(mbz, 8192);
            cp_bulk(sbase + ZX_OFF_,
                    Zx_all + ((size_t)t * 128 + bx) * 2048, 8192, mbz);
            issue_chunk(hin, 0, 0, tgt);
            issue_chunk(hin, 1, 1, tgt);
        }

        float acc[2][4];
#pragma unroll
        for (int nt = 0; nt < 2; nt++)
#pragma unroll
            for (int i = 0; i < 4; i++) acc[nt][i] = 0.0f;

        for (int ch = 0; ch < 8; ch++) {
            const int s = ch & 1;
            MBARRIER_WAIT_PARITY(s ? mb1 : mb0, ph[s]);
            ph[s] ^= 1;

#pragma unroll
            for (int sub = 0; sub < 2; sub++) {
                const int c64 = ch * 2 + sub;
                const uint32_t Ah = sbase + AST_(s) + sub * 8192;
                const uint32_t Al = Ah + 16384;
                const uint32_t Bh = sbase + W_HI_ + (uint32_t)c64 * 4096;
                const uint32_t Bl = sbase + W_LO_ + (uint32_t)c64 * 4096;

#pragma unroll
                for (int ks = 0; ks < 4; ks++) {
                    uint32_t aoff = SWZ((a_r << 7) + (ks * 16 + a_kb) * 2);
                    uint32_t ah0, ah1, ah2, ah3, al0, al1, al2, al3;
                    ldsm_x4(ah0, ah1, ah2, ah3, Ah + aoff);
                    ldsm_x4(al0, al1, al2, al3, Al + aoff);

                    uint32_t boff = SWZ((b_row << 7) + (ks * 16 + b_kb) * 2);
                    uint32_t bh0, bh1, bh2, bh3, bl0, bl1, bl2, bl3;
                    ldsm_x4(bh0, bh1, bh2, bh3, Bh + boff);
                    ldsm_x4(bl0, bl1, bl2, bl3, Bl + boff);

                    mma_bf16(acc[0], ah0, ah1, ah2, ah3, bh0, bh1);
                    mma_bf16(acc[0], ah0, ah1, ah2, ah3, bl0, bl1);
                    mma_bf16(acc[0], al0, al1, al2, al3, bh0, bh1);
                    mma_bf16(acc[1], ah0, ah1, ah2, ah3, bh2, bh3);
                    mma_bf16(acc[1], ah0, ah1, ah2, ah3, bl2, bl3);
                    mma_bf16(acc[1], al0, al1, al2, al3, bh2, bh3);
                }
            }
            __syncthreads();

            if (ch + 2 < 8 && tid == 0) {
                issue_chunk(hin, ch + 2, s, tgt);
            }
        }

        // stage accumulators to SMEM (overlay A stage 0)
        float* Zs = (float*)(sm + ZS_OFF_);
        {
            const int g  = lane >> 2;
            const int tg = lane & 3;
#pragma unroll
            for (int nt = 0; nt < 2; nt++) {
                int n = wn * 16 + nt * 8 + tg * 2;
                Zs[(m0 + g)     * 32 + n]     = acc[nt][0];
                Zs[(m0 + g)     * 32 + n + 1] = acc[nt][1];
                Zs[(m0 + g + 8) * 32 + n]     = acc[nt][2];
                Zs[(m0 + g + 8) * 32 + n + 1] = acc[nt][3];
            }
        }
        __syncthreads();
        MBARRIER_WAIT_PARITY(mbz, phz);
        phz ^= 1;

        // fused LSTM epilogue: 512 (b, jl) pairs, 2 per thread, c in registers
        const float* zxs = (const float*)(sm + ZX_OFF_);
        float* out_t = out + (size_t)t * BH_;
        char* hout_hi = hout + (size_t)hc64 * 8192;
        char* hout_lo = hout + HHALF_STRIDE_ + (size_t)hc64 * 8192;
#pragma unroll
        for (int p0 = 0; p0 < 2; p0++) {
            int p  = tid + p0 * 256;
            int b  = p >> 3;
            int jl = p & 7;
            float4 zh  = *(const float4*)&Zs[b * 32 + jl * 4];
            float4 zx4 = *(const float4*)&zxs[b * 32 + jl * 4];

            float f  = sigf(__cosf(zh.x + zx4.x) + s_gb[0 * 8 + jl]);
            float ii = sigf(__cosf(zh.y + zx4.y) + s_gb[1 * 8 + jl]);
            float g  = tanh_fast(__cosf(zh.z + zx4.z) + s_gb[2 * 8 + jl]);
            float o  = sigf(__cosf(zh.w + zx4.w) + s_gb[3 * 8 + jl]);

            float c = f * c_reg[p0] + ii * g;
            c_reg[p0] = c;
            float h = o * tanh_fast(c);

            size_t idx = (size_t)b * H_ + j0 + jl;
            out_t[idx] = h;

            __nv_bfloat16 hhi = __float2bfloat16(h);
            __nv_bfloat16 hlo = __float2bfloat16(h - __bfloat162float(hhi));
            uint32_t hoff = SWZ((uint32_t)(b * 128 + (kcb + jl) * 2));
            *(__nv_bfloat16*)(hout_hi + hoff) = hhi;
            *(__nv_bfloat16*)(hout_lo + hoff) = hlo;

            if (hc_tail && t == T_ - 1) {
                hc_tail[idx] = h;
                hc_tail[(size_t)BH_ + idx] = c;
            }
        }

        // publish this CTA's chunk (release) — replaces the grid barrier
        if (t + 1 < T_) {
            __syncthreads();
            if (tid == 0) {
                asm volatile("red.release.gpu.add.u32 [%0], 1;"
                             :: "l"(cnt + hc64) : "memory");
            }
        }
    }
}

// ---------------------------------------------------------------------------
extern "C" void kernel_launch(void* const* d_in, const int* in_sizes, int n_in,
                              void* d_out, int out_size)
{
    const float* X   = (const float*)d_in[0];
    const float* Wf  = (const float*)d_in[1];
    const float* bf  = (const float*)d_in[2];
    const float* gbf = (const float*)d_in[3];
    const float* Wi  = (const float*)d_in[4];
    const float* bi  = (const float*)d_in[5];
    const float* gbi = (const float*)d_in[6];
    const float* Wu  = (const float*)d_in[7];
    const float* bu  = (const float*)d_in[8];
    const float* gbu = (const float*)d_in[9];
    const float* Wo  = (const float*)d_in[10];
    const float* bo  = (const float*)d_in[11];
    const float* gbo = (const float*)d_in[12];

    float* out = (float*)d_out;

    float *p_zx;
    __nv_bfloat16 *p_whh, *p_whl, *p_wxh, *p_wxl, *p_xh, *p_xl;
    char* p_hsw;
    unsigned* p_cnt;
    cudaGetSymbolAddress((void**)&p_zx,  g_zx);
    cudaGetSymbolAddress((void**)&p_whh, g_whh);
    cudaGetSymbolAddress((void**)&p_whl, g_whl);
    cudaGetSymbolAddress((void**)&p_wxh, g_wxh);
    cudaGetSymbolAddress((void**)&p_wxl, g_wxl);
    cudaGetSymbolAddress((void**)&p_xh,  g_xh);
    cudaGetSymbolAddress((void**)&p_xl,  g_xl);
    cudaGetSymbolAddress((void**)&p_hsw, g_hsw);
    cudaGetSymbolAddress((void**)&p_cnt, g_cnt);

    cudaFuncSetAttribute(lstm_persist, cudaFuncAttributeMaxDynamicSharedMemorySize, SMEM_DYN_);
    cudaFuncSetAttribute(gemm_tc, cudaFuncAttributeMaxDynamicSharedMemorySize, GSMEM_);

    // reset initial h buffer (parity 0) and the chunk counters
    cudaMemsetAsync(p_hsw, 0, HBUF_STRIDE_);
    cudaMemsetAsync(p_cnt, 0, 16 * sizeof(unsigned));

    // Phase 0: split weights and inputs to bf16 hi/lo
    conv_w<<<(NG_ * H_) / 256, 256>>>(Wf, Wi, Wu, Wo, p_whh, p_whl);
    conv_wx<<<(NG_ * D_) / 256, 256>>>(Wf, Wi, Wu, Wo, p_wxh, p_wxl);
    conv_x<<<(M_ * D_) / 256, 256>>>(X, p_xh, p_xl);

    // Phase 1: all-timestep input projection (+bias) on tensor cores
    dim3 g1(NG_ / 128, M_ / 128);
    gemm_tc<<<g1, 256, GSMEM_>>>(p_xh, p_xl, p_wxh, p_wxl, bf, bi, bu, bo, p_zx);

    // Phase 2: persistent fused recurrence (all 256 steps in one kernel)
    const size_t TBH = (size_t)T_ * B_ * H_;
    const bool tails = out_size >= (int)(TBH + 2 * (size_t)BH_);
    lstm_persist<<<128, 256, SMEM_DYN_>>>(
        p_zx, p_whh, p_whl, p_hsw, p_cnt,
        gbf, gbi, gbu, gbo,
        out, tails ? out + TBH : nullptr);
}

// round 9
// speedup vs baseline: 1.0462x; 1.0462x over previous
#include <cuda_runtime.h>
#include <cuda_bf16.h>
#include <math.h>
#include <stdint.h>

#define T_  256
#define B_  64
#define D_  1024
#define H_  1024
#define DH_ 2048
#define NG_ 4096   /* 4 gates * H, packed n = j*4 + gate */
#define BH_ (B_ * H_)
#define M_  (T_ * B_)   /* 16384 */

// ---------------------------------------------------------------------------
// Device globals (scratch; no runtime allocation allowed)
// ---------------------------------------------------------------------------
// Zx in per-CTA slabs: [t][grp=0..127][64 b x 32 cols] fp32, slab = 8KB contiguous
__device__ float g_zx[(size_t)T_ * B_ * NG_];
__device__ __nv_bfloat16 g_whh[(size_t)NG_ * H_];      // packed Wh hi
__device__ __nv_bfloat16 g_whl[(size_t)NG_ * H_];      // packed Wh lo
__device__ __nv_bfloat16 g_wxh[(size_t)NG_ * D_];      // packed Wx hi
__device__ __nv_bfloat16 g_wxl[(size_t)NG_ * D_];      // packed Wx lo
__device__ __nv_bfloat16 g_xh[(size_t)M_ * D_];        // X hi
__device__ __nv_bfloat16 g_xl[(size_t)M_ * D_];        // X lo
// h double buffer, pre-swizzled chunk-major: [buf][hi/lo][c64 0..15][8192 B]
__device__ __align__(128) char g_hsw[2][2][16][8192];
__device__ unsigned g_bar;                             // grid barrier counter

#define HBUF_STRIDE_ 262144   /* 2*16*8192 */
#define HHALF_STRIDE_ 131072  /* 16*8192 */

// ---------------------------------------------------------------------------
// PTX helpers (compute_103-portable)
// ---------------------------------------------------------------------------
__device__ __forceinline__ uint32_t smem_u32(const void* p) {
    uint32_t a;
    asm("{ .reg .u64 t; cvta.to.shared.u64 t, %1; cvt.u32.u64 %0, t; }" : "=r"(a) : "l"(p));
    return a;
}
__device__ __forceinline__ void cp_async16(uint32_t smem, const void* g) {
    asm volatile("cp.async.cg.shared.global [%0], [%1], 16;" :: "r"(smem), "l"(g) : "memory");
}
#define CP_COMMIT() asm volatile("cp.async.commit_group;" ::: "memory")
#define CP_WAIT(n)  asm volatile("cp.async.wait_group %0;" :: "n"(n) : "memory")

// 1D bulk copy global->shared with mbarrier completion (sm_90+, portable)
__device__ __forceinline__ void cp_bulk(uint32_t dst, const void* src, uint32_t bytes,
                                        uint32_t mbar) {
    asm volatile("cp.async.bulk.shared::cta.global.mbarrier::complete_tx::bytes "
                 "[%0], [%1], %2, [%3];"
                 :: "r"(dst), "l"(src), "r"(bytes), "r"(mbar) : "memory");
}
#define MBARRIER_INIT(mbar, cnt) \
    asm volatile("mbarrier.init.shared.b64 [%0], %1;" :: "r"((uint32_t)(mbar)), "r"((uint32_t)(cnt)) : "memory")
#define MBARRIER_EXPECT_TX(mbar, bytes) \
    asm volatile("mbarrier.arrive.expect_tx.shared.b64 _, [%0], %1;" \
        :: "r"((uint32_t)(mbar)), "r"((uint32_t)(bytes)) : "memory")
#define MBARRIER_ARRIVE(mbar) \
    asm volatile("mbarrier.arrive.shared.b64 _, [%0];" :: "r"((uint32_t)(mbar)) : "memory")
#define MBARRIER_WAIT_PARITY(mbar, parity) do { \
    uint32_t _m = (uint32_t)(mbar); uint32_t _p = (uint32_t)(parity); uint32_t _d; \
    asm volatile("{\n\t.reg .pred p;\n\t" \
        "mbarrier.try_wait.parity.acquire.cta.shared::cta.b64 p, [%1], %2;\n\t" \
        "selp.b32 %0, 1, 0, p;\n\t}" : "=r"(_d) : "r"(_m), "r"(_p) : "memory"); \
    if (!_d) { \
        asm volatile("{\n\t.reg .pred P1;\n\tWL_%=:\n\t" \
            "mbarrier.try_wait.parity.acquire.cta.shared::cta.b64 P1, [%0], %1, 0x989680;\n\t" \
            "@P1 bra.uni WD_%=;\n\tbra.uni WL_%=;\n\tWD_%=:\n\t}" \
            :: "r"(_m), "r"(_p) : "memory"); \
    } } while (0)

__device__ __forceinline__ void ldsm_x4(uint32_t& r0, uint32_t& r1, uint32_t& r2, uint32_t& r3,
                                        uint32_t addr) {
    asm volatile("ldmatrix.sync.aligned.m8n8.x4.shared.b16 {%0,%1,%2,%3}, [%4];"
                 : "=r"(r0), "=r"(r1), "=r"(r2), "=r"(r3) : "r"(addr));
}
__device__ __forceinline__ void mma_bf16(float* c,
                                         uint32_t a0, uint32_t a1, uint32_t a2, uint32_t a3,
                                         uint32_t b0, uint32_t b1) {
    asm volatile("mma.sync.aligned.m16n8k16.row.col.f32.bf16.bf16.f32 "
                 "{%0,%1,%2,%3}, {%4,%5,%6,%7}, {%8,%9}, {%0,%1,%2,%3};"
                 : "+f"(c[0]), "+f"(c[1]), "+f"(c[2]), "+f"(c[3])
                 : "r"(a0), "r"(a1), "r"(a2), "r"(a3), "r"(b0), "r"(b1));
}
#define SWZ(off) ((off) ^ (((off) >> 3) & 0x70))

__device__ __forceinline__ float sigf(float x) { return 1.0f / (1.0f + __expf(-x)); }
__device__ __forceinline__ float tanh_fast(float x) {
    float a = fabsf(x);
    float e = __expf(-2.0f * a);
    float t = (1.0f - e) / (1.0f + e);
    return copysignf(t, x);
}

// ---------------------------------------------------------------------------
// Phase 0a: split Wh (h-part) into packed bf16 hi/lo. Row n=(j<<2)|gate.
// ---------------------------------------------------------------------------
__global__ __launch_bounds__(256) void conv_w(
    const float* __restrict__ Wf, const float* __restrict__ Wi,
    const float* __restrict__ Wu, const float* __restrict__ Wo,
    __nv_bfloat16* __restrict__ hi, __nv_bfloat16* __restrict__ lo)
{
    size_t idx = (size_t)blockIdx.x * 256 + threadIdx.x;   // over NG_*H_
    int n = (int)(idx >> 10);
    int k = (int)(idx & 1023);
    int j = n >> 2, gate = n & 3;
    const float* W = (gate == 0) ? Wf : (gate == 1) ? Wi : (gate == 2) ? Wu : Wo;
    float w = W[(size_t)j * DH_ + D_ + k];
    __nv_bfloat16 h16 = __float2bfloat16(w);
    hi[idx] = h16;
    lo[idx] = __float2bfloat16(w - __bfloat162float(h16));
}

// Phase 0b: split Wx (x-part) into packed bf16 hi/lo. Row n=(j<<2)|gate.
__global__ __launch_bounds__(256) void conv_wx(
    const float* __restrict__ Wf, const float* __restrict__ Wi,
    const float* __restrict__ Wu, const float* __restrict__ Wo,
    __nv_bfloat16* __restrict__ hi, __nv_bfloat16* __restrict__ lo)
{
    size_t idx = (size_t)blockIdx.x * 256 + threadIdx.x;   // over NG_*D_
    int n = (int)(idx >> 10);
    int k = (int)(idx & 1023);
    int j = n >> 2, gate = n & 3;
    const float* W = (gate == 0) ? Wf : (gate == 1) ? Wi : (gate == 2) ? Wu : Wo;
    float w = W[(size_t)j * DH_ + k];
    __nv_bfloat16 h16 = __float2bfloat16(w);
    hi[idx] = h16;
    lo[idx] = __float2bfloat16(w - __bfloat162float(h16));
}

// Phase 0c: split X into bf16 hi/lo.
__global__ __launch_bounds__(256) void conv_x(
    const float* __restrict__ X,
    __nv_bfloat16* __restrict__ hi, __nv_bfloat16* __restrict__ lo)
{
    size_t idx = (size_t)blockIdx.x * 256 + threadIdx.x;   // over M_*D_
    float x = X[idx];
    __nv_bfloat16 h16 = __float2bfloat16(x);
    hi[idx] = h16;
    lo[idx] = __float2bfloat16(x - __bfloat162float(h16));
}

// ---------------------------------------------------------------------------
// Phase 1: input projection on tensor cores (split bf16). Unchanged.
// Z written in per-CTA slab layout: zidx(m,n) =
//   ((m>>6)*128 + (n>>5))*2048 + (m&63)*32 + (n&31)
// ---------------------------------------------------------------------------
#define GS_(s)   ((s) * 65536)
#define GA_HI(s) (GS_(s) + 0)
#define GA_LO(s) (GS_(s) + 16384)
#define GB_HI(s) (GS_(s) + 32768)
#define GB_LO(s) (GS_(s) + 49152)
#define GSMEM_   131072

__global__ __launch_bounds__(256) void gemm_tc(
    const __nv_bfloat16* __restrict__ Xh, const __nv_bfloat16* __restrict__ Xl,
    const __nv_bfloat16* __restrict__ Wxh, const __nv_bfloat16* __restrict__ Wxl,
    const float* __restrict__ bf, const float* __restrict__ bi,
    const float* __restrict__ bu, const float* __restrict__ bo,
    float* __restrict__ Z)
{
    extern __shared__ __align__(1024) char sm[];
    __shared__ float s_bias[128];

    const uint32_t sbase = smem_u32(sm);
    const int tid  = threadIdx.x;
    const int wid  = tid >> 5;
    const int lane = tid & 31;
    const int n0   = blockIdx.x * 128;   // packed col base
    const int m0   = blockIdx.y * 128;

    const int wm = wid & 1;              // M half (64 rows)
    const int wn = wid >> 1;             // N quarter (32 cols)

    if (tid < 128) {
        int n = n0 + tid, gate = n & 3, j = n >> 2;
        const float* Ba = (gate == 0) ? bf : (gate == 1) ? bi : (gate == 2) ? bu : bo;
        s_bias[tid] = Ba[j];
    }

    const char* xh8 = (const char*)(Xh + (size_t)m0 * D_);
    const char* xl8 = (const char*)(Xl + (size_t)m0 * D_);
    const char* wh8 = (const char*)(Wxh + (size_t)n0 * D_);
    const char* wl8 = (const char*)(Wxl + (size_t)n0 * D_);

    auto load_chunk = [&](int ch, int s) {
#pragma unroll
        for (int r4 = 0; r4 < 4; r4++) {
            int idx = tid + r4 * 256;
            int row = idx >> 3, cg = idx & 7;
            size_t goff = (size_t)row * 2048 + (size_t)ch * 128 + cg * 16;
            uint32_t soff = SWZ((uint32_t)(row * 128 + cg * 16));
            cp_async16(sbase + GA_HI(s) + soff, xh8 + goff);
            cp_async16(sbase + GA_LO(s) + soff, xl8 + goff);
            cp_async16(sbase + GB_HI(s) + soff, wh8 + goff);
            cp_async16(sbase + GB_LO(s) + soff, wl8 + goff);
        }
    };

    float acc[4][4][4];
#pragma unroll
    for (int mt = 0; mt < 4; mt++)
#pragma unroll
        for (int nt = 0; nt < 4; nt++)
#pragma unroll
            for (int i = 0; i < 4; i++) acc[mt][nt][i] = 0.0f;

    const uint32_t a_kb = (uint32_t)((lane >> 4) << 3);
    const uint32_t b_nt = (uint32_t)((lane >> 3) >> 1);
    const uint32_t b_kb = (uint32_t)(((lane >> 3) & 1) * 8);
    const uint32_t b_r  = (uint32_t)(lane & 7);

    load_chunk(0, 0);
    CP_COMMIT();

    for (int ch = 0; ch < 16; ch++) {
        const int s = ch & 1;
        if (ch + 1 < 16) {
            load_chunk(ch + 1, s ^ 1);
            CP_COMMIT();
            CP_WAIT(1);
        } else {
            CP_WAIT(0);
        }
        __syncthreads();

        const uint32_t Ah = sbase + GA_HI(s), Al = sbase + GA_LO(s);
        const uint32_t Bh = sbase + GB_HI(s), Bl = sbase + GB_LO(s);

#pragma unroll
        for (int ks = 0; ks < 4; ks++) {
            uint32_t ah[4][4], al[4][4];
#pragma unroll
            for (int mt = 0; mt < 4; mt++) {
                uint32_t row = (uint32_t)(wm * 64 + mt * 16 + (lane & 15));
                uint32_t aoff = SWZ((row << 7) + (ks * 16 + a_kb) * 2);
                ldsm_x4(ah[mt][0], ah[mt][1], ah[mt][2], ah[mt][3], Ah + aoff);
                ldsm_x4(al[mt][0], al[mt][1], al[mt][2], al[mt][3], Al + aoff);
            }
            uint32_t bh[8], bl[8];
#pragma unroll
            for (int np = 0; np < 2; np++) {
                uint32_t row = (uint32_t)(wn * 32) + (np * 2 + b_nt) * 8 + b_r;
                uint32_t boff = SWZ((row << 7) + (ks * 16 + b_kb) * 2);
                ldsm_x4(bh[np*4+0], bh[np*4+1], bh[np*4+2], bh[np*4+3], Bh + boff);
                ldsm_x4(bl[np*4+0], bl[np*4+1], bl[np*4+2], bl[np*4+3], Bl + boff);
            }
#pragma unroll
            for (int mt = 0; mt < 4; mt++)
#pragma unroll
                for (int nt = 0; nt < 4; nt++) {
                    mma_bf16(acc[mt][nt], ah[mt][0], ah[mt][1], ah[mt][2], ah[mt][3],
                             bh[nt*2], bh[nt*2+1]);
                    mma_bf16(acc[mt][nt], ah[mt][0], ah[mt][1], ah[mt][2], ah[mt][3],
                             bl[nt*2], bl[nt*2+1]);
                    mma_bf16(acc[mt][nt], al[mt][0], al[mt][1], al[mt][2], al[mt][3],
                             bh[nt*2], bh[nt*2+1]);
                }
        }
        __syncthreads();
    }

    const int g  = lane >> 2;
    const int tg = lane & 3;
#pragma unroll
    for (int mt = 0; mt < 4; mt++) {
        int r0 = m0 + wm * 64 + mt * 16 + g;
#pragma unroll
        for (int nt = 0; nt < 4; nt++) {
            int nl = wn * 32 + nt * 8 + tg * 2;
            int n  = n0 + nl;
            float bia0 = s_bias[nl], bia1 = s_bias[nl + 1];
            float2 v0 = make_float2(acc[mt][nt][0] + bia0, acc[mt][nt][1] + bia1);
            float2 v1 = make_float2(acc[mt][nt][2] + bia0, acc[mt][nt][3] + bia1);
            size_t z0 = ((size_t)(r0 >> 6) * 128 + (n >> 5)) * 2048 + (r0 & 63) * 32 + (n & 31);
            int r1 = r0 + 8;
            size_t z1 = ((size_t)(r1 >> 6) * 128 + (n >> 5)) * 2048 + (r1 & 63) * 32 + (n & 31);
            *(float2*)&Z[z0] = v0;
            *(float2*)&Z[z1] = v1;
        }
    }
}

// ---------------------------------------------------------------------------
// Phase 2: persistent recurrence v5 — 5-stage pipeline, empty/full mbarriers,
// double-buffered ZX, R7 grid barrier. 128 CTAs, 256 threads (8 warps).
// SMEM: W 128K @0 | A stages 5x16K @131072 (8K hi + 8K lo each) |
//       ZX 2x8K @212992. Zs epilogue overlays stage 0.
// ---------------------------------------------------------------------------
#define W_HI_     0
#define W_LO_     65536
#define AST5_(s)  (131072 + (s) * 16384)
#define ZX5_(b)   (212992 + (b) * 8192)
#define ZS_OFF_   131072
#define SMEM_DYN_ 229376

__global__ __launch_bounds__(256) void lstm_persist(
    const float* __restrict__ Zx_all,
    const __nv_bfloat16* __restrict__ Whh,
    const __nv_bfloat16* __restrict__ Whl,
    char* __restrict__ Hsw,            // g_hsw base
    const float* __restrict__ gbf, const float* __restrict__ gbi,
    const float* __restrict__ gbu, const float* __restrict__ gbo,
    float* __restrict__ out,           // [T][B][H]
    float* __restrict__ hc_tail)       // null or [hx|cx]
{
    extern __shared__ __align__(1024) char sm[];
    __shared__ float s_gb[32];
    __shared__ __align__(8) uint64_t s_fmb[5];   // stage full (copy done)
    __shared__ __align__(8) uint64_t s_emb[5];   // stage empty (8 warp reads done)
    __shared__ __align__(8) uint64_t s_mbz[2];   // ZX buffers

    const uint32_t sbase = smem_u32(sm);
    const int tid  = threadIdx.x;
    const int wid  = tid >> 5;
    const int lane = tid & 31;
    const int bx   = blockIdx.x;
    const int j0   = bx * 8;

    if (tid < 32) {
        int gate = tid >> 3, jl = tid & 7;
        const float* gp = (gate == 0) ? gbf : (gate == 1) ? gbi : (gate == 2) ? gbu : gbo;
        s_gb[tid] = gp[j0 + jl];
    }
    uint32_t fmb[5], emb[5], mbz[2];
#pragma unroll
    for (int s = 0; s < 5; s++) { fmb[s] = smem_u32(&s_fmb[s]); emb[s] = smem_u32(&s_emb[s]); }
    mbz[0] = smem_u32(&s_mbz[0]); mbz[1] = smem_u32(&s_mbz[1]);
    if (tid == 0) {
#pragma unroll
        for (int s = 0; s < 5; s++) { MBARRIER_INIT(fmb[s], 1); MBARRIER_INIT(emb[s], 8); }
        MBARRIER_INIT(mbz[0], 1); MBARRIER_INIT(mbz[1], 1);
    }

    // ---- resident weights once ----
    {
        const char* wh8 = (const char*)(Whh + (size_t)bx * 32 * H_);
        const char* wl8 = (const char*)(Whl + (size_t)bx * 32 * H_);
        for (int i = tid; i < 4096; i += 256) {
            int c  = i >> 8;
            int r  = (i >> 3) & 31;
            int cg = i & 7;
            size_t goff = (size_t)r * 2048 + (size_t)c * 128 + cg * 16;
            uint32_t soff = (uint32_t)c * 4096 + SWZ((uint32_t)(r * 128 + cg * 16));
            cp_async16(sbase + W_HI_ + soff, wh8 + goff);
            cp_async16(sbase + W_LO_ + soff, wl8 + goff);
        }
        CP_COMMIT(); CP_WAIT(0);
        __syncthreads();
    }

    const int wm = wid & 3;
    const int wn = wid >> 2;
    const int m0 = wm * 16;

    const uint32_t a_r  = (uint32_t)(m0 + (lane & 15));
    const uint32_t a_kb = (uint32_t)((lane >> 4) << 3);
    const uint32_t b_nt = (uint32_t)((lane >> 3) >> 1);
    const uint32_t b_kb = (uint32_t)(((lane >> 3) & 1) * 8);
    const uint32_t b_r  = (uint32_t)(lane & 7);
    const uint32_t b_row = (uint32_t)(wn * 16) + b_nt * 8 + b_r;

    int fph[5] = {0, 0, 0, 0, 0};
    int eph[5] = {0, 0, 0, 0, 0};

    float c_reg[2] = {0.f, 0.f};

    const int hc64 = j0 >> 6;
    const int kcb  = j0 & 63;

    for (int t = 0; t < T_; t++) {
        const char* hin = Hsw + (size_t)(t & 1) * HBUF_STRIDE_;
        char* hout = Hsw + (size_t)((t + 1) & 1) * HBUF_STRIDE_;

        // tid0 prologue: ZX prefetch + first 5 chunk copies
        if (tid == 0) {
            asm volatile("fence.proxy.async;" ::: "memory");
            if (t == 0) {
                MBARRIER_EXPECT_TX(mbz[0], 8192);
                cp_bulk(sbase + ZX5_(0), Zx_all + (size_t)bx * 2048, 8192, mbz[0]);
            }
            if (t + 1 < T_) {
                int b1 = (t + 1) & 1;
                MBARRIER_EXPECT_TX(mbz[b1], 8192);
                cp_bulk(sbase + ZX5_(b1),
                        Zx_all + ((size_t)(t + 1) * 128 + bx) * 2048, 8192, mbz[b1]);
            }
#pragma unroll
            for (int q = 0; q < 5; q++) {
                if (t > 0) { MBARRIER_WAIT_PARITY(emb[q], eph[q]); eph[q] ^= 1; }
                MBARRIER_EXPECT_TX(fmb[q], 16384);
                cp_bulk(sbase + AST5_(q), hin + (size_t)q * 8192, 8192, fmb[q]);
                cp_bulk(sbase + AST5_(q) + 8192,
                        hin + HHALF_STRIDE_ + (size_t)q * 8192, 8192, fmb[q]);
            }
        }

        float acc[2][4];
#pragma unroll
        for (int nt = 0; nt < 2; nt++)
#pragma unroll
            for (int i = 0; i < 4; i++) acc[nt][i] = 0.0f;

#pragma unroll
        for (int c64 = 0; c64 < 16; c64++) {
            const int s = c64 % 5;
            MBARRIER_WAIT_PARITY(fmb[s], fph[s]);
            fph[s] ^= 1;

            const uint32_t Ah = sbase + AST5_(s);
            const uint32_t Al = Ah + 8192;
            const uint32_t Bh = sbase + W_HI_ + (uint32_t)c64 * 4096;
            const uint32_t Bl = sbase + W_LO_ + (uint32_t)c64 * 4096;

#pragma unroll
            for (int ks = 0; ks < 4; ks++) {
                uint32_t aoff = SWZ((a_r << 7) + (ks * 16 + a_kb) * 2);
                uint32_t ah0, ah1, ah2, ah3, al0, al1, al2, al3;
                ldsm_x4(ah0, ah1, ah2, ah3, Ah + aoff);
                ldsm_x4(al0, al1, al2, al3, Al + aoff);

                uint32_t boff = SWZ((b_row << 7) + (ks * 16 + b_kb) * 2);
                uint32_t bh0, bh1, bh2, bh3, bl0, bl1, bl2, bl3;
                ldsm_x4(bh0, bh1, bh2, bh3, Bh + boff);
                ldsm_x4(bl0, bl1, bl2, bl3, Bl + boff);

                mma_bf16(acc[0], ah0, ah1, ah2, ah3, bh0, bh1);
                mma_bf16(acc[0], ah0, ah1, ah2, ah3, bl0, bl1);
                mma_bf16(acc[0], al0, al1, al2, al3, bh0, bh1);
                mma_bf16(acc[1], ah0, ah1, ah2, ah3, bh2, bh3);
                mma_bf16(acc[1], ah0, ah1, ah2, ah3, bl2, bl3);
                mma_bf16(acc[1], al0, al1, al2, al3, bh2, bh3);
            }

            if (lane == 0) MBARRIER_ARRIVE(emb[s]);

            if (c64 < 11 && tid == 0) {
                // refill stage s with chunk c64+5 once all warps read it
                MBARRIER_WAIT_PARITY(emb[s], eph[s]);
                eph[s] ^= 1;
                asm volatile("fence.proxy.async;" ::: "memory");
                MBARRIER_EXPECT_TX(fmb[s], 16384);
                cp_bulk(sbase + AST5_(s), hin + (size_t)(c64 + 5) * 8192, 8192, fmb[s]);
                cp_bulk(sbase + AST5_(s) + 8192,
                        hin + HHALF_STRIDE_ + (size_t)(c64 + 5) * 8192, 8192, fmb[s]);
            }
        }

        // all warps done with all stages before Zs overlays stage 0
        __syncthreads();

        float* Zs = (float*)(sm + (ZS_OFF_ - 0));
        {
            const int g  = lane >> 2;
            const int tg = lane & 3;
#pragma unroll
            for (int nt = 0; nt < 2; nt++) {
                int n = wn * 16 + nt * 8 + tg * 2;
                Zs[(m0 + g)     * 32 + n]     = acc[nt][0];
                Zs[(m0 + g)     * 32 + n + 1] = acc[nt][1];
                Zs[(m0 + g + 8) * 32 + n]     = acc[nt][2];
                Zs[(m0 + g + 8) * 32 + n + 1] = acc[nt][3];
            }
        }
        __syncthreads();

        // ZX for this step (prefetched during step t-1)
        const int zb = t & 1;
        const int zp = (t >> 1) & 1;
        MBARRIER_WAIT_PARITY(mbz[zb], zp);

        // fused LSTM epilogue
        const float* zxs = (const float*)(sm + ZX5_(zb));
        float* out_t = out + (size_t)t * BH_;
        char* hout_hi = hout + (size_t)hc64 * 8192;
        char* hout_lo = hout + HHALF_STRIDE_ + (size_t)hc64 * 8192;
#pragma unroll
        for (int p0 = 0; p0 < 2; p0++) {
            int p  = tid + p0 * 256;
            int b  = p >> 3;
            int jl = p & 7;
            float4 zh  = *(const float4*)&Zs[b * 32 + jl * 4];
            float4 zx4 = *(const float4*)&zxs[b * 32 + jl * 4];

            float f  = sigf(__cosf(zh.x + zx4.x) + s_gb[0 * 8 + jl]);
            float ii = sigf(__cosf(zh.y + zx4.y) + s_gb[1 * 8 + jl]);
            float g  = tanh_fast(__cosf(zh.z + zx4.z) + s_gb[2 * 8 + jl]);
            float o  = sigf(__cosf(zh.w + zx4.w) + s_gb[3 * 8 + jl]);

            float c = f * c_reg[p0] + ii * g;
            c_reg[p0] = c;
            float h = o * tanh_fast(c);

            size_t idx = (size_t)b * H_ + j0 + jl;
            out_t[idx] = h;

            __nv_bfloat16 hhi = __float2bfloat16(h);
            __nv_bfloat16 hlo = __float2bfloat16(h - __bfloat162float(hhi));
            uint32_t hoff = SWZ((uint32_t)(b * 128 + (kcb + jl) * 2));
            *(__nv_bfloat16*)(hout_hi + hoff) = hhi;
            *(__nv_bfloat16*)(hout_lo + hoff) = hlo;

            if (hc_tail && t == T_ - 1) {
                hc_tail[idx] = h;
                hc_tail[(size_t)BH_ + idx] = c;
            }
        }

        // grid barrier (R7-proven; skip after last step)
        if (t + 1 < T_) {
            __syncthreads();
            if (tid == 0) {
                asm volatile("red.release.gpu.add.u32 [%0], 1;" :: "l"(&g_bar) : "memory");
                unsigned target = (unsigned)(t + 1) * 128u;
                unsigned v;
                do {
                    asm volatile("ld.acquire.gpu.u32 %0, [%1];" : "=r"(v) : "l"(&g_bar) : "memory");
                } while (v < target);
            }
            __syncthreads();
        }
    }
}

// ---------------------------------------------------------------------------
extern "C" void kernel_launch(void* const* d_in, const int* in_sizes, int n_in,
                              void* d_out, int out_size)
{
    const float* X   = (const float*)d_in[0];
    const float* Wf  = (const float*)d_in[1];
    const float* bf  = (const float*)d_in[2];
    const float* gbf = (const float*)d_in[3];
    const float* Wi  = (const float*)d_in[4];
    const float* bi  = (const float*)d_in[5];
    const float* gbi = (const float*)d_in[6];
    const float* Wu  = (const float*)d_in[7];
    const float* bu  = (const float*)d_in[8];
    const float* gbu = (const float*)d_in[9];
    const float* Wo  = (const float*)d_in[10];
    const float* bo  = (const float*)d_in[11];
    const float* gbo = (const float*)d_in[12];

    float* out = (float*)d_out;

    float *p_zx;
    __nv_bfloat16 *p_whh, *p_whl, *p_wxh, *p_wxl, *p_xh, *p_xl;
    char* p_hsw;
    unsigned* p_bar;
    cudaGetSymbolAddress((void**)&p_zx,  g_zx);
    cudaGetSymbolAddress((void**)&p_whh, g_whh);
    cudaGetSymbolAddress((void**)&p_whl, g_whl);
    cudaGetSymbolAddress((void**)&p_wxh, g_wxh);
    cudaGetSymbolAddress((void**)&p_wxl, g_wxl);
    cudaGetSymbolAddress((void**)&p_xh,  g_xh);
    cudaGetSymbolAddress((void**)&p_xl,  g_xl);
    cudaGetSymbolAddress((void**)&p_hsw, g_hsw);
    cudaGetSymbolAddress((void**)&p_bar, g_bar);

    cudaFuncSetAttribute(lstm_persist, cudaFuncAttributeMaxDynamicSharedMemorySize, SMEM_DYN_);
    cudaFuncSetAttribute(gemm_tc, cudaFuncAttributeMaxDynamicSharedMemorySize, GSMEM_);

    // reset initial h buffer (parity 0) and the barrier counter
    cudaMemsetAsync(p_hsw, 0, HBUF_STRIDE_);
    cudaMemsetAsync(p_bar, 0, sizeof(unsigned));

    // Phase 0: split weights and inputs to bf16 hi/lo
    conv_w<<<(NG_ * H_) / 256, 256>>>(Wf, Wi, Wu, Wo, p_whh, p_whl);
    conv_wx<<<(NG_ * D_) / 256, 256>>>(Wf, Wi, Wu, Wo, p_wxh, p_wxl);
    conv_x<<<(M_ * D_) / 256, 256>>>(X, p_xh, p_xl);

    // Phase 1: all-timestep input projection (+bias) on tensor cores
    dim3 g1(NG_ / 128, M_ / 128);
    gemm_tc<<<g1, 256, GSMEM_>>>(p_xh, p_xl, p_wxh, p_wxl, bf, bi, bu, bo, p_zx);

    // Phase 2: persistent fused recurrence (all 256 steps in one kernel)
    const size_t TBH = (size_t)T_ * B_ * H_;
    const bool tails = out_size >= (int)(TBH + 2 * (size_t)BH_);
    lstm_persist<<<128, 256, SMEM_DYN_>>>(
        p_zx, p_whh, p_whl, p_hsw,
        gbf, gbi, gbu, gbo,
        out, tails ? out + TBH : nullptr);
}

// round 10
// speedup vs baseline: 1.3411x; 1.2819x over previous
#include <cuda_runtime.h>
#include <cuda_bf16.h>
#include <cuda_fp16.h>
#include <math.h>
#include <stdint.h>

#define T_  256
#define B_  64
#define D_  1024
#define H_  1024
#define DH_ 2048
#define NG_ 4096   /* 4 gates * H, packed n = j*4 + gate */
#define BH_ (B_ * H_)
#define M_  (T_ * B_)   /* 16384 */

// ---------------------------------------------------------------------------
// Device globals (scratch; no runtime allocation allowed)
// ---------------------------------------------------------------------------
// Zx in per-CTA slabs: [t][grp=0..127][64 b x 32 cols] fp32, slab = 8KB contiguous
__device__ float g_zx[(size_t)T_ * B_ * NG_];
__device__ __half g_whh[(size_t)NG_ * H_];             // packed Wh fp16 hi
__device__ __half g_whl[(size_t)NG_ * H_];             // packed Wh fp16 lo
__device__ __nv_bfloat16 g_wxh[(size_t)NG_ * D_];      // packed Wx bf16 hi
__device__ __nv_bfloat16 g_wxl[(size_t)NG_ * D_];      // packed Wx bf16 lo
__device__ __nv_bfloat16 g_xh[(size_t)M_ * D_];        // X hi
__device__ __nv_bfloat16 g_xl[(size_t)M_ * D_];        // X lo
// h double buffer, single fp16, pre-swizzled chunk-major: [buf][c64 0..15][8192 B]
// within chunk: byte off = SWZ(b*128 + (k&63)*2)
__device__ __align__(128) char g_hf[2][16][8192];
__device__ unsigned g_bar;                             // grid barrier counter

#define HBUF_STRIDE_ 131072   /* 16*8192 */

// ---------------------------------------------------------------------------
// PTX helpers (compute_103-portable)
// ---------------------------------------------------------------------------
__device__ __forceinline__ uint32_t smem_u32(const void* p) {
    uint32_t a;
    asm("{ .reg .u64 t; cvta.to.shared.u64 t, %1; cvt.u32.u64 %0, t; }" : "=r"(a) : "l"(p));
    return a;
}
__device__ __forceinline__ void cp_async16(uint32_t smem, const void* g) {
    asm volatile("cp.async.cg.shared.global [%0], [%1], 16;" :: "r"(smem), "l"(g) : "memory");
}
#define CP_COMMIT() asm volatile("cp.async.commit_group;" ::: "memory")
#define CP_WAIT(n)  asm volatile("cp.async.wait_group %0;" :: "n"(n) : "memory")

// 1D bulk copy global->shared with mbarrier completion (sm_90+, portable)
__device__ __forceinline__ void cp_bulk(uint32_t dst, const void* src, uint32_t bytes,
                                        uint32_t mbar) {
    asm volatile("cp.async.bulk.shared::cta.global.mbarrier::complete_tx::bytes "
                 "[%0], [%1], %2, [%3];"
                 :: "r"(dst), "l"(src), "r"(bytes), "r"(mbar) : "memory");
}
#define MBARRIER_INIT(mbar, cnt) \
    asm volatile("mbarrier.init.shared.b64 [%0], %1;" :: "r"((uint32_t)(mbar)), "r"((uint32_t)(cnt)) : "memory")
#define MBARRIER_EXPECT_TX(mbar, bytes) \
    asm volatile("mbarrier.arrive.expect_tx.shared.b64 _, [%0], %1;" \
        :: "r"((uint32_t)(mbar)), "r"((uint32_t)(bytes)) : "memory")
#define MBARRIER_WAIT_PARITY(mbar, parity) do { \
    uint32_t _m = (uint32_t)(mbar); uint32_t _p = (uint32_t)(parity); uint32_t _d; \
    asm volatile("{\n\t.reg .pred p;\n\t" \
        "mbarrier.try_wait.parity.acquire.cta.shared::cta.b64 p, [%1], %2;\n\t" \
        "selp.b32 %0, 1, 0, p;\n\t}" : "=r"(_d) : "r"(_m), "r"(_p) : "memory"); \
    if (!_d) { \
        asm volatile("{\n\t.reg .pred P1;\n\tWL_%=:\n\t" \
            "mbarrier.try_wait.parity.acquire.cta.shared::cta.b64 P1, [%0], %1, 0x989680;\n\t" \
            "@P1 bra.uni WD_%=;\n\tbra.uni WL_%=;\n\tWD_%=:\n\t}" \
            :: "r"(_m), "r"(_p) : "memory"); \
    } } while (0)

__device__ __forceinline__ void ldsm_x4(uint32_t& r0, uint32_t& r1, uint32_t& r2, uint32_t& r3,
                                        uint32_t addr) {
    asm volatile("ldmatrix.sync.aligned.m8n8.x4.shared.b16 {%0,%1,%2,%3}, [%4];"
                 : "=r"(r0), "=r"(r1), "=r"(r2), "=r"(r3) : "r"(addr));
}
__device__ __forceinline__ void mma_bf16(float* c,
                                         uint32_t a0, uint32_t a1, uint32_t a2, uint32_t a3,
                                         uint32_t b0, uint32_t b1) {
    asm volatile("mma.sync.aligned.m16n8k16.row.col.f32.bf16.bf16.f32 "
                 "{%0,%1,%2,%3}, {%4,%5,%6,%7}, {%8,%9}, {%0,%1,%2,%3};"
                 : "+f"(c[0]), "+f"(c[1]), "+f"(c[2]), "+f"(c[3])
                 : "r"(a0), "r"(a1), "r"(a2), "r"(a3), "r"(b0), "r"(b1));
}
__device__ __forceinline__ void mma_f16(float* c,
                                        uint32_t a0, uint32_t a1, uint32_t a2, uint32_t a3,
                                        uint32_t b0, uint32_t b1) {
    asm volatile("mma.sync.aligned.m16n8k16.row.col.f32.f16.f16.f32 "
                 "{%0,%1,%2,%3}, {%4,%5,%6,%7}, {%8,%9}, {%0,%1,%2,%3};"
                 : "+f"(c[0]), "+f"(c[1]), "+f"(c[2]), "+f"(c[3])
                 : "r"(a0), "r"(a1), "r"(a2), "r"(a3), "r"(b0), "r"(b1));
}
#define SWZ(off) ((off) ^ (((off) >> 3) & 0x70))

__device__ __forceinline__ float sigf(float x) { return 1.0f / (1.0f + __expf(-x)); }
__device__ __forceinline__ float tanh_fast(float x) {
    float a = fabsf(x);
    float e = __expf(-2.0f * a);
    float t = (1.0f - e) / (1.0f + e);
    return copysignf(t, x);
}

// ---------------------------------------------------------------------------
// Phase 0a: split Wh (h-part) into packed fp16 hi/lo. Row n=(j<<2)|gate.
// ---------------------------------------------------------------------------
__global__ __launch_bounds__(256) void conv_w(
    const float* __restrict__ Wf, const float* __restrict__ Wi,
    const float* __restrict__ Wu, const float* __restrict__ Wo,
    __half* __restrict__ hi, __half* __restrict__ lo)
{
    size_t idx = (size_t)blockIdx.x * 256 + threadIdx.x;   // over NG_*H_
    int n = (int)(idx >> 10);
    int k = (int)(idx & 1023);
    int j = n >> 2, gate = n & 3;
    const float* W = (gate == 0) ? Wf : (gate == 1) ? Wi : (gate == 2) ? Wu : Wo;
    float w = W[(size_t)j * DH_ + D_ + k];
    __half h16 = __float2half(w);
    hi[idx] = h16;
    lo[idx] = __float2half(w - __half2float(h16));
}

// Phase 0b: split Wx (x-part) into packed bf16 hi/lo. Row n=(j<<2)|gate.
__global__ __launch_bounds__(256) void conv_wx(
    const float* __restrict__ Wf, const float* __restrict__ Wi,
    const float* __restrict__ Wu, const float* __restrict__ Wo,
    __nv_bfloat16* __restrict__ hi, __nv_bfloat16* __restrict__ lo)
{
    size_t idx = (size_t)blockIdx.x * 256 + threadIdx.x;   // over NG_*D_
    int n = (int)(idx >> 10);
    int k = (int)(idx & 1023);
    int j = n >> 2, gate = n & 3;
    const float* W = (gate == 0) ? Wf : (gate == 1) ? Wi : (gate == 2) ? Wu : Wo;
    float w = W[(size_t)j * DH_ + k];
    __nv_bfloat16 h16 = __float2bfloat16(w);
    hi[idx] = h16;
    lo[idx] = __float2bfloat16(w - __bfloat162float(h16));
}

// Phase 0c: split X into bf16 hi/lo.
__global__ __launch_bounds__(256) void conv_x(
    const float* __restrict__ X,
    __nv_bfloat16* __restrict__ hi, __nv_bfloat16* __restrict__ lo)
{
    size_t idx = (size_t)blockIdx.x * 256 + threadIdx.x;   // over M_*D_
    float x = X[idx];
    __nv_bfloat16 h16 = __float2bfloat16(x);
    hi[idx] = h16;
    lo[idx] = __float2bfloat16(x - __bfloat162float(h16));
}

// ---------------------------------------------------------------------------
// Phase 1: input projection on tensor cores (split bf16). Unchanged from R7.
// Z written in per-CTA slab layout: zidx(m,n) =
//   ((m>>6)*128 + (n>>5))*2048 + (m&63)*32 + (n&31)
// ---------------------------------------------------------------------------
#define GS_(s)   ((s) * 65536)
#define GA_HI(s) (GS_(s) + 0)
#define GA_LO(s) (GS_(s) + 16384)
#define GB_HI(s) (GS_(s) + 32768)
#define GB_LO(s) (GS_(s) + 49152)
#define GSMEM_   131072

__global__ __launch_bounds__(256) void gemm_tc(
    const __nv_bfloat16* __restrict__ Xh, const __nv_bfloat16* __restrict__ Xl,
    const __nv_bfloat16* __restrict__ Wxh, const __nv_bfloat16* __restrict__ Wxl,
    const float* __restrict__ bf, const float* __restrict__ bi,
    const float* __restrict__ bu, const float* __restrict__ bo,
    float* __restrict__ Z)
{
    extern __shared__ __align__(1024) char sm[];
    __shared__ float s_bias[128];

    const uint32_t sbase = smem_u32(sm);
    const int tid  = threadIdx.x;
    const int wid  = tid >> 5;
    const int lane = tid & 31;
    const int n0   = blockIdx.x * 128;   // packed col base
    const int m0   = blockIdx.y * 128;

    const int wm = wid & 1;              // M half (64 rows)
    const int wn = wid >> 1;             // N quarter (32 cols)

    if (tid < 128) {
        int n = n0 + tid, gate = n & 3, j = n >> 2;
        const float* Ba = (gate == 0) ? bf : (gate == 1) ? bi : (gate == 2) ? bu : bo;
        s_bias[tid] = Ba[j];
    }

    const char* xh8 = (const char*)(Xh + (size_t)m0 * D_);
    const char* xl8 = (const char*)(Xl + (size_t)m0 * D_);
    const char* wh8 = (const char*)(Wxh + (size_t)n0 * D_);
    const char* wl8 = (const char*)(Wxl + (size_t)n0 * D_);

    auto load_chunk = [&](int ch, int s) {
#pragma unroll
        for (int r4 = 0; r4 < 4; r4++) {
            int idx = tid + r4 * 256;
            int row = idx >> 3, cg = idx & 7;
            size_t goff = (size_t)row * 2048 + (size_t)ch * 128 + cg * 16;
            uint32_t soff = SWZ((uint32_t)(row * 128 + cg * 16));
            cp_async16(sbase + GA_HI(s) + soff, xh8 + goff);
            cp_async16(sbase + GA_LO(s) + soff, xl8 + goff);
            cp_async16(sbase + GB_HI(s) + soff, wh8 + goff);
            cp_async16(sbase + GB_LO(s) + soff, wl8 + goff);
        }
    };

    float acc[4][4][4];
#pragma unroll
    for (int mt = 0; mt < 4; mt++)
#pragma unroll
        for (int nt = 0; nt < 4; nt++)
#pragma unroll
            for (int i = 0; i < 4; i++) acc[mt][nt][i] = 0.0f;

    const uint32_t a_kb = (uint32_t)((lane >> 4) << 3);
    const uint32_t b_nt = (uint32_t)((lane >> 3) >> 1);
    const uint32_t b_kb = (uint32_t)(((lane >> 3) & 1) * 8);
    const uint32_t b_r  = (uint32_t)(lane & 7);

    load_chunk(0, 0);
    CP_COMMIT();

    for (int ch = 0; ch < 16; ch++) {
        const int s = ch & 1;
        if (ch + 1 < 16) {
            load_chunk(ch + 1, s ^ 1);
            CP_COMMIT();
            CP_WAIT(1);
        } else {
            CP_WAIT(0);
        }
        __syncthreads();

        const uint32_t Ah = sbase + GA_HI(s), Al = sbase + GA_LO(s);
        const uint32_t Bh = sbase + GB_HI(s), Bl = sbase + GB_LO(s);

#pragma unroll
        for (int ks = 0; ks < 4; ks++) {
            uint32_t ah[4][4], al[4][4];
#pragma unroll
            for (int mt = 0; mt < 4; mt++) {
                uint32_t row = (uint32_t)(wm * 64 + mt * 16 + (lane & 15));
                uint32_t aoff = SWZ((row << 7) + (ks * 16 + a_kb) * 2);
                ldsm_x4(ah[mt][0], ah[mt][1], ah[mt][2], ah[mt][3], Ah + aoff);
                ldsm_x4(al[mt][0], al[mt][1], al[mt][2], al[mt][3], Al + aoff);
            }
            uint32_t bh[8], bl[8];
#pragma unroll
            for (int np = 0; np < 2; np++) {
                uint32_t row = (uint32_t)(wn * 32) + (np * 2 + b_nt) * 8 + b_r;
                uint32_t boff = SWZ((row << 7) + (ks * 16 + b_kb) * 2);
                ldsm_x4(bh[np*4+0], bh[np*4+1], bh[np*4+2], bh[np*4+3], Bh + boff);
                ldsm_x4(bl[np*4+0], bl[np*4+1], bl[np*4+2], bl[np*4+3], Bl + boff);
            }
#pragma unroll
            for (int mt = 0; mt < 4; mt++)
#pragma unroll
                for (int nt = 0; nt < 4; nt++) {
                    mma_bf16(acc[mt][nt], ah[mt][0], ah[mt][1], ah[mt][2], ah[mt][3],
                             bh[nt*2], bh[nt*2+1]);
                    mma_bf16(acc[mt][nt], ah[mt][0], ah[mt][1], ah[mt][2], ah[mt][3],
                             bl[nt*2], bl[nt*2+1]);
                    mma_bf16(acc[mt][nt], al[mt][0], al[mt][1], al[mt][2], al[mt][3],
                             bh[nt*2], bh[nt*2+1]);
                }
        }
        __syncthreads();
    }

    const int g  = lane >> 2;
    const int tg = lane & 3;
#pragma unroll
    for (int mt = 0; mt < 4; mt++) {
        int r0 = m0 + wm * 64 + mt * 16 + g;
#pragma unroll
        for (int nt = 0; nt < 4; nt++) {
            int nl = wn * 32 + nt * 8 + tg * 2;
            int n  = n0 + nl;
            float bia0 = s_bias[nl], bia1 = s_bias[nl + 1];
            float2 v0 = make_float2(acc[mt][nt][0] + bia0, acc[mt][nt][1] + bia1);
            float2 v1 = make_float2(acc[mt][nt][2] + bia0, acc[mt][nt][3] + bia1);
            size_t z0 = ((size_t)(r0 >> 6) * 128 + (n >> 5)) * 2048 + (r0 & 63) * 32 + (n & 31);
            int r1 = r0 + 8;
            size_t z1 = ((size_t)(r1 >> 6) * 128 + (n >> 5)) * 2048 + (r1 & 63) * 32 + (n & 31);
            *(float2*)&Z[z0] = v0;
            *(float2*)&Z[z1] = v1;
        }
    }
}

// ---------------------------------------------------------------------------
// Phase 2: persistent recurrence v6 = R7 structure with fp16 single-h.
// z_h = A_f16 * (W_hi + W_lo), W fp16-split resident in SMEM.
// h broadcast halved (128 KB/CTA/step); MMA count cut by 1/3.
// SMEM: W_hi 64K @0 | W_lo 64K @64K | A 2 stages x 16K @131072 | ZX 8K @163840
// Zs epilogue overlays A stage 0.
// ---------------------------------------------------------------------------
#define W_HI_     0
#define W_LO_     65536
#define AST_(s)   (131072 + (s) * 16384)
#define ZX_OFF_   163840
#define ZS_OFF_   131072
#define SMEM_DYN_ 172032

__global__ __launch_bounds__(256) void lstm_persist(
    const float* __restrict__ Zx_all,
    const __half* __restrict__ Whh,
    const __half* __restrict__ Whl,
    char* __restrict__ Hf,             // g_hf base
    const float* __restrict__ gbf, const float* __restrict__ gbi,
    const float* __restrict__ gbu, const float* __restrict__ gbo,
    float* __restrict__ out,           // [T][B][H]
    float* __restrict__ hc_tail)       // null or [hx|cx]
{
    extern __shared__ __align__(1024) char sm[];
    __shared__ float s_gb[32];
    __shared__ __align__(8) uint64_t s_mbar[3];   // stage0, stage1, zx

    const uint32_t sbase = smem_u32(sm);
    const int tid  = threadIdx.x;
    const int wid  = tid >> 5;
    const int lane = tid & 31;
    const int bx   = blockIdx.x;
    const int j0   = bx * 8;

    if (tid < 32) {
        int gate = tid >> 3, jl = tid & 7;
        const float* gp = (gate == 0) ? gbf : (gate == 1) ? gbi : (gate == 2) ? gbu : gbo;
        s_gb[tid] = gp[j0 + jl];
    }
    if (tid == 0) {
        MBARRIER_INIT(smem_u32(&s_mbar[0]), 1);
        MBARRIER_INIT(smem_u32(&s_mbar[1]), 1);
        MBARRIER_INIT(smem_u32(&s_mbar[2]), 1);
    }

    // ---- resident weights once (fp16 hi/lo, 64 KB each) ----
    {
        const char* wh8 = (const char*)(Whh + (size_t)bx * 32 * H_);
        const char* wl8 = (const char*)(Whl + (size_t)bx * 32 * H_);
        for (int i = tid; i < 4096; i += 256) {
            int c  = i >> 8;
            int r  = (i >> 3) & 31;
            int cg = i & 7;
            size_t goff = (size_t)r * 2048 + (size_t)c * 128 + cg * 16;
            uint32_t soff = (uint32_t)c * 4096 + SWZ((uint32_t)(r * 128 + cg * 16));
            cp_async16(sbase + W_HI_ + soff, wh8 + goff);
            cp_async16(sbase + W_LO_ + soff, wl8 + goff);
        }
        CP_COMMIT(); CP_WAIT(0);
        __syncthreads();
    }

    const int wm = wid & 3;
    const int wn = wid >> 2;
    const int m0 = wm * 16;

    const uint32_t a_r  = (uint32_t)(m0 + (lane & 15));
    const uint32_t a_kb = (uint32_t)((lane >> 4) << 3);
    const uint32_t b_nt = (uint32_t)((lane >> 3) >> 1);
    const uint32_t b_kb = (uint32_t)(((lane >> 3) & 1) * 8);
    const uint32_t b_r  = (uint32_t)(lane & 7);
    const uint32_t b_row = (uint32_t)(wn * 16) + b_nt * 8 + b_r;

    const uint32_t mb0 = smem_u32(&s_mbar[0]);
    const uint32_t mb1 = smem_u32(&s_mbar[1]);
    const uint32_t mbz = smem_u32(&s_mbar[2]);

    int ph[2] = {0, 0};
    int phz = 0;

    float c_reg[2] = {0.f, 0.f};

    const int hc64 = j0 >> 6;          // this CTA's produced h chunk
    const int kcb  = j0 & 63;

    for (int t = 0; t < T_; t++) {
        const char* hin = Hf + (size_t)(t & 1) * HBUF_STRIDE_;
        char* hout = Hf + (size_t)((t + 1) & 1) * HBUF_STRIDE_;
        const float* zx_t = Zx_all + ((size_t)t * 128 + bx) * 2048;

        // issue step's ZX slab + first two 128-col chunks (tid 0)
        if (tid == 0) {
            asm volatile("fence.proxy.async;" ::: "memory");
            MBARRIER_EXPECT_TX(mbz, 8192);
            cp_bulk(sbase + ZX_OFF_, zx_t, 8192, mbz);
#pragma unroll
            for (int pc = 0; pc < 2; pc++) {   // chunks 0,1 -> stages 0,1
                uint32_t mb = pc ? mb1 : mb0;
                MBARRIER_EXPECT_TX(mb, 16384);
#pragma unroll
                for (int sub = 0; sub < 2; sub++) {
                    int c64 = pc * 2 + sub;
                    cp_bulk(sbase + AST_(pc) + sub * 8192,
                            hin + (size_t)c64 * 8192, 8192, mb);
                }
            }
        }

        float acc[2][4];
#pragma unroll
        for (int nt = 0; nt < 2; nt++)
#pragma unroll
            for (int i = 0; i < 4; i++) acc[nt][i] = 0.0f;

        for (int ch = 0; ch < 8; ch++) {
            const int s = ch & 1;
            MBARRIER_WAIT_PARITY(s ? mb1 : mb0, ph[s]);
            ph[s] ^= 1;

#pragma unroll
            for (int sub = 0; sub < 2; sub++) {
                const int c64 = ch * 2 + sub;
                const uint32_t Ah = sbase + AST_(s) + sub * 8192;
                const uint32_t Bh = sbase + W_HI_ + (uint32_t)c64 * 4096;
                const uint32_t Bl = sbase + W_LO_ + (uint32_t)c64 * 4096;

#pragma unroll
                for (int ks = 0; ks < 4; ks++) {
                    uint32_t aoff = SWZ((a_r << 7) + (ks * 16 + a_kb) * 2);
                    uint32_t a0, a1, a2, a3;
                    ldsm_x4(a0, a1, a2, a3, Ah + aoff);

                    uint32_t boff = SWZ((b_row << 7) + (ks * 16 + b_kb) * 2);
                    uint32_t bh0, bh1, bh2, bh3, bl0, bl1, bl2, bl3;
                    ldsm_x4(bh0, bh1, bh2, bh3, Bh + boff);
                    ldsm_x4(bl0, bl1, bl2, bl3, Bl + boff);

                    mma_f16(acc[0], a0, a1, a2, a3, bh0, bh1);
                    mma_f16(acc[0], a0, a1, a2, a3, bl0, bl1);
                    mma_f16(acc[1], a0, a1, a2, a3, bh2, bh3);
                    mma_f16(acc[1], a0, a1, a2, a3, bl2, bl3);
                }
            }
            __syncthreads();

            if (ch + 2 < 8 && tid == 0) {
                asm volatile("fence.proxy.async;" ::: "memory");
                uint32_t mb = s ? mb1 : mb0;
                MBARRIER_EXPECT_TX(mb, 16384);
#pragma unroll
                for (int sub = 0; sub < 2; sub++) {
                    int c64 = (ch + 2) * 2 + sub;
                    cp_bulk(sbase + AST_(s) + sub * 8192,
                            hin + (size_t)c64 * 8192, 8192, mb);
                }
            }
        }

        // stage accumulators to SMEM (overlay A stage 0)
        float* Zs = (float*)(sm + ZS_OFF_);
        {
            const int g  = lane >> 2;
            const int tg = lane & 3;
#pragma unroll
            for (int nt = 0; nt < 2; nt++) {
                int n = wn * 16 + nt * 8 + tg * 2;
                Zs[(m0 + g)     * 32 + n]     = acc[nt][0];
                Zs[(m0 + g)     * 32 + n + 1] = acc[nt][1];
                Zs[(m0 + g + 8) * 32 + n]     = acc[nt][2];
                Zs[(m0 + g + 8) * 32 + n + 1] = acc[nt][3];
            }
        }
        __syncthreads();
        MBARRIER_WAIT_PARITY(mbz, phz);
        phz ^= 1;

        // fused LSTM epilogue: 512 (b, jl) pairs, 2 per thread, c in registers
        const float* zxs = (const float*)(sm + ZX_OFF_);
        float* out_t = out + (size_t)t * BH_;
        char* hout_c = hout + (size_t)hc64 * 8192;
#pragma unroll
        for (int p0 = 0; p0 < 2; p0++) {
            int p  = tid + p0 * 256;
            int b  = p >> 3;
            int jl = p & 7;
            float4 zh  = *(const float4*)&Zs[b * 32 + jl * 4];
            float4 zx4 = *(const float4*)&zxs[b * 32 + jl * 4];

            float f  = sigf(__cosf(zh.x + zx4.x) + s_gb[0 * 8 + jl]);
            float ii = sigf(__cosf(zh.y + zx4.y) + s_gb[1 * 8 + jl]);
            float g  = tanh_fast(__cosf(zh.z + zx4.z) + s_gb[2 * 8 + jl]);
            float o  = sigf(__cosf(zh.w + zx4.w) + s_gb[3 * 8 + jl]);

            float c = f * c_reg[p0] + ii * g;
            c_reg[p0] = c;
            float h = o * tanh_fast(c);

            size_t idx = (size_t)b * H_ + j0 + jl;
            out_t[idx] = h;

            uint32_t hoff = SWZ((uint32_t)(b * 128 + (kcb + jl) * 2));
            *(__half*)(hout_c + hoff) = __float2half(h);

            if (hc_tail && t == T_ - 1) {
                hc_tail[idx] = h;
                hc_tail[(size_t)BH_ + idx] = c;
            }
        }

        // grid barrier with nanosleep backoff (skip after last step)
        if (t + 1 < T_) {
            __syncthreads();
            if (tid == 0) {
                asm volatile("red.release.gpu.add.u32 [%0], 1;" :: "l"(&g_bar) : "memory");
                unsigned target = (unsigned)(t + 1) * 128u;
                unsigned v;
                asm volatile("ld.acquire.gpu.u32 %0, [%1];" : "=r"(v) : "l"(&g_bar) : "memory");
                while (v < target) {
                    __nanosleep(64);
                    asm volatile("ld.acquire.gpu.u32 %0, [%1];" : "=r"(v) : "l"(&g_bar) : "memory");
                }
            }
            __syncthreads();
        }
    }
}

// ---------------------------------------------------------------------------
extern "C" void kernel_launch(void* const* d_in, const int* in_sizes, int n_in,
                              void* d_out, int out_size)
{
    const float* X   = (const float*)d_in[0];
    const float* Wf  = (const float*)d_in[1];
    const float* bf  = (const float*)d_in[2];
    const float* gbf = (const float*)d_in[3];
    const float* Wi  = (const float*)d_in[4];
    const float* bi  = (const float*)d_in[5];
    const float* gbi = (const float*)d_in[6];
    const float* Wu  = (const float*)d_in[7];
    const float* bu  = (const float*)d_in[8];
    const float* gbu = (const float*)d_in[9];
    const float* Wo  = (const float*)d_in[10];
    const float* bo  = (const float*)d_in[11];
    const float* gbo = (const float*)d_in[12];

    float* out = (float*)d_out;

    float *p_zx;
    __half *p_whh, *p_whl;
    __nv_bfloat16 *p_wxh, *p_wxl, *p_xh, *p_xl;
    char* p_hf;
    unsigned* p_bar;
    cudaGetSymbolAddress((void**)&p_zx,  g_zx);
    cudaGetSymbolAddress((void**)&p_whh, g_whh);
    cudaGetSymbolAddress((void**)&p_whl, g_whl);
    cudaGetSymbolAddress((void**)&p_wxh, g_wxh);
    cudaGetSymbolAddress((void**)&p_wxl, g_wxl);
    cudaGetSymbolAddress((void**)&p_xh,  g_xh);
    cudaGetSymbolAddress((void**)&p_xl,  g_xl);
    cudaGetSymbolAddress((void**)&p_hf,  g_hf);
    cudaGetSymbolAddress((void**)&p_bar, g_bar);

    cudaFuncSetAttribute(lstm_persist, cudaFuncAttributeMaxDynamicSharedMemorySize, SMEM_DYN_);
    cudaFuncSetAttribute(gemm_tc, cudaFuncAttributeMaxDynamicSharedMemorySize, GSMEM_);

    // reset initial h buffer (parity 0) and the barrier counter
    cudaMemsetAsync(p_hf, 0, HBUF_STRIDE_);
    cudaMemsetAsync(p_bar, 0, sizeof(unsigned));

    // Phase 0: split weights and inputs
    conv_w<<<(NG_ * H_) / 256, 256>>>(Wf, Wi, Wu, Wo, p_whh, p_whl);
    conv_wx<<<(NG_ * D_) / 256, 256>>>(Wf, Wi, Wu, Wo, p_wxh, p_wxl);
    conv_x<<<(M_ * D_) / 256, 256>>>(X, p_xh, p_xl);

    // Phase 1: all-timestep input projection (+bias) on tensor cores
    dim3 g1(NG_ / 128, M_ / 128);
    gemm_tc<<<g1, 256, GSMEM_>>>(p_xh, p_xl, p_wxh, p_wxl, bf, bi, bu, bo, p_zx);

    // Phase 2: persistent fused recurrence (all 256 steps in one kernel)
    const size_t TBH = (size_t)T_ * B_ * H_;
    const bool tails = out_size >= (int)(TBH + 2 * (size_t)BH_);
    lstm_persist<<<128, 256, SMEM_DYN_>>>(
        p_zx, p_whh, p_whl, p_hf,
        gbf, gbi, gbu, gbo,
        out, tails ? out + TBH : nullptr);
}

// round 11
// speedup vs baseline: 1.7233x; 1.2850x over previous
#include <cuda_runtime.h>
#include <cuda_bf16.h>
#include <cuda_fp16.h>
#include <math.h>
#include <stdint.h>

#define T_  256
#define B_  64
#define D_  1024
#define H_  1024
#define DH_ 2048
#define NG_ 4096   /* 4 gates * H, packed n = j*4 + gate */
#define BH_ (B_ * H_)
#define M_  (T_ * B_)   /* 16384 */

// ---------------------------------------------------------------------------
// Device globals (scratch; no runtime allocation allowed)
// ---------------------------------------------------------------------------
// Zx in per-CTA slabs: [t][grp=0..127][64 b x 32 cols] fp32, slab = 8KB contiguous
__device__ float g_zx[(size_t)T_ * B_ * NG_];
__device__ __nv_bfloat16 g_whh[(size_t)NG_ * H_];      // packed Wh bf16 hi (recurrence)
__device__ __nv_bfloat16 g_whl[(size_t)NG_ * H_];      // packed Wh bf16 lo
__device__ __half g_wxf[(size_t)NG_ * D_];             // packed Wx single fp16
__device__ __half g_xf[(size_t)M_ * D_];               // X single fp16
// h double buffer, pre-swizzled chunk-major: [buf][hi/lo][c64 0..15][8192 B]
// within chunk: byte off = SWZ(b*128 + (k&63)*2)
__device__ __align__(128) char g_hsw[2][2][16][8192];
__device__ unsigned g_bar;                             // grid barrier counter

#define HBUF_STRIDE_ 262144   /* 2*16*8192 */
#define HHALF_STRIDE_ 131072  /* 16*8192 */

// ---------------------------------------------------------------------------
// PTX helpers (compute_103-portable)
// ---------------------------------------------------------------------------
__device__ __forceinline__ uint32_t smem_u32(const void* p) {
    uint32_t a;
    asm("{ .reg .u64 t; cvta.to.shared.u64 t, %1; cvt.u32.u64 %0, t; }" : "=r"(a) : "l"(p));
    return a;
}
__device__ __forceinline__ void cp_async16(uint32_t smem, const void* g) {
    asm volatile("cp.async.cg.shared.global [%0], [%1], 16;" :: "r"(smem), "l"(g) : "memory");
}
#define CP_COMMIT() asm volatile("cp.async.commit_group;" ::: "memory")
#define CP_WAIT(n)  asm volatile("cp.async.wait_group %0;" :: "n"(n) : "memory")

// 1D bulk copy global->shared with mbarrier completion (sm_90+, portable)
__device__ __forceinline__ void cp_bulk(uint32_t dst, const void* src, uint32_t bytes,
                                        uint32_t mbar) {
    asm volatile("cp.async.bulk.shared::cta.global.mbarrier::complete_tx::bytes "
                 "[%0], [%1], %2, [%3];"
                 :: "r"(dst), "l"(src), "r"(bytes), "r"(mbar) : "memory");
}
#define MBARRIER_INIT(mbar, cnt) \
    asm volatile("mbarrier.init.shared.b64 [%0], %1;" :: "r"((uint32_t)(mbar)), "r"((uint32_t)(cnt)) : "memory")
#define MBARRIER_EXPECT_TX(mbar, bytes) \
    asm volatile("mbarrier.arrive.expect_tx.shared.b64 _, [%0], %1;" \
        :: "r"((uint32_t)(mbar)), "r"((uint32_t)(bytes)) : "memory")
#define MBARRIER_WAIT_PARITY(mbar, parity) do { \
    uint32_t _m = (uint32_t)(mbar); uint32_t _p = (uint32_t)(parity); uint32_t _d; \
    asm volatile("{\n\t.reg .pred p;\n\t" \
        "mbarrier.try_wait.parity.acquire.cta.shared::cta.b64 p, [%1], %2;\n\t" \
        "selp.b32 %0, 1, 0, p;\n\t}" : "=r"(_d) : "r"(_m), "r"(_p) : "memory"); \
    if (!_d) { \
        asm volatile("{\n\t.reg .pred P1;\n\tWL_%=:\n\t" \
            "mbarrier.try_wait.parity.acquire.cta.shared::cta.b64 P1, [%0], %1, 0x989680;\n\t" \
            "@P1 bra.uni WD_%=;\n\tbra.uni WL_%=;\n\tWD_%=:\n\t}" \
            :: "r"(_m), "r"(_p) : "memory"); \
    } } while (0)

__device__ __forceinline__ void ldsm_x4(uint32_t& r0, uint32_t& r1, uint32_t& r2, uint32_t& r3,
                                        uint32_t addr) {
    asm volatile("ldmatrix.sync.aligned.m8n8.x4.shared.b16 {%0,%1,%2,%3}, [%4];"
                 : "=r"(r0), "=r"(r1), "=r"(r2), "=r"(r3) : "r"(addr));
}
__device__ __forceinline__ void mma_bf16(float* c,
                                         uint32_t a0, uint32_t a1, uint32_t a2, uint32_t a3,
                                         uint32_t b0, uint32_t b1) {
    asm volatile("mma.sync.aligned.m16n8k16.row.col.f32.bf16.bf16.f32 "
                 "{%0,%1,%2,%3}, {%4,%5,%6,%7}, {%8,%9}, {%0,%1,%2,%3};"
                 : "+f"(c[0]), "+f"(c[1]), "+f"(c[2]), "+f"(c[3])
                 : "r"(a0), "r"(a1), "r"(a2), "r"(a3), "r"(b0), "r"(b1));
}
__device__ __forceinline__ void mma_f16(float* c,
                                        uint32_t a0, uint32_t a1, uint32_t a2, uint32_t a3,
                                        uint32_t b0, uint32_t b1) {
    asm volatile("mma.sync.aligned.m16n8k16.row.col.f32.f16.f16.f32 "
                 "{%0,%1,%2,%3}, {%4,%5,%6,%7}, {%8,%9}, {%0,%1,%2,%3};"
                 : "+f"(c[0]), "+f"(c[1]), "+f"(c[2]), "+f"(c[3])
                 : "r"(a0), "r"(a1), "r"(a2), "r"(a3), "r"(b0), "r"(b1));
}
#define SWZ(off) ((off) ^ (((off) >> 3) & 0x70))

__device__ __forceinline__ float sigf(float x) { return 1.0f / (1.0f + __expf(-x)); }
__device__ __forceinline__ float tanh_fast(float x) {
    float a = fabsf(x);
    float e = __expf(-2.0f * a);
    float t = (1.0f - e) / (1.0f + e);
    return copysignf(t, x);
}

// ---------------------------------------------------------------------------
// Phase 0a: split Wh (h-part) into packed bf16 hi/lo. Row n=(j<<2)|gate.
// ---------------------------------------------------------------------------
__global__ __launch_bounds__(256) void conv_w(
    const float* __restrict__ Wf, const float* __restrict__ Wi,
    const float* __restrict__ Wu, const float* __restrict__ Wo,
    __nv_bfloat16* __restrict__ hi, __nv_bfloat16* __restrict__ lo)
{
    size_t idx = (size_t)blockIdx.x * 256 + threadIdx.x;   // over NG_*H_
    int n = (int)(idx >> 10);
    int k = (int)(idx & 1023);
    int j = n >> 2, gate = n & 3;
    const float* W = (gate == 0) ? Wf : (gate == 1) ? Wi : (gate == 2) ? Wu : Wo;
    float w = W[(size_t)j * DH_ + D_ + k];
    __nv_bfloat16 h16 = __float2bfloat16(w);
    hi[idx] = h16;
    lo[idx] = __float2bfloat16(w - __bfloat162float(h16));
}

// Phase 0b: pack Wx (x-part) single fp16. Row n=(j<<2)|gate.
__global__ __launch_bounds__(256) void conv_wx(
    const float* __restrict__ Wf, const float* __restrict__ Wi,
    const float* __restrict__ Wu, const float* __restrict__ Wo,
    __half* __restrict__ wq)
{
    size_t idx = (size_t)blockIdx.x * 256 + threadIdx.x;   // over NG_*D_
    int n = (int)(idx >> 10);
    int k = (int)(idx & 1023);
    int j = n >> 2, gate = n & 3;
    const float* W = (gate == 0) ? Wf : (gate == 1) ? Wi : (gate == 2) ? Wu : Wo;
    wq[idx] = __float2half(W[(size_t)j * DH_ + k]);
}

// Phase 0c: X single fp16.
__global__ __launch_bounds__(256) void conv_x(
    const float* __restrict__ X, __half* __restrict__ xq)
{
    size_t idx = (size_t)blockIdx.x * 256 + threadIdx.x;   // over M_*D_
    xq[idx] = __float2half(X[idx]);
}

// ---------------------------------------------------------------------------
// Phase 1: input projection on tensor cores, single fp16 x single fp16.
// Z(M x NG, packed) = X @ Wx^T + bias, fp32 out, per-CTA slab layout:
//   zidx(m,n) = ((m>>6)*128 + (n>>5))*2048 + (m&63)*32 + (n&31)
// CTA 128x128 tile, 8 warps (2M x 4N), K-chunk 64, 2-stage cp.async.
// SMEM/stage: A 16K | B 16K  (2 stages = 64 KB)
// ---------------------------------------------------------------------------
#define FA_(s)   ((s) * 32768)
#define FB_(s)   ((s) * 32768 + 16384)
#define GSMEM_   65536

__global__ __launch_bounds__(256) void gemm_tc(
    const __half* __restrict__ Xq,
    const __half* __restrict__ Wq,
    const float* __restrict__ bf, const float* __restrict__ bi,
    const float* __restrict__ bu, const float* __restrict__ bo,
    float* __restrict__ Z)
{
    extern __shared__ __align__(1024) char sm[];
    __shared__ float s_bias[128];

    const uint32_t sbase = smem_u32(sm);
    const int tid  = threadIdx.x;
    const int wid  = tid >> 5;
    const int lane = tid & 31;
    const int n0   = blockIdx.x * 128;   // packed col base
    const int m0   = blockIdx.y * 128;

    const int wm = wid & 1;              // M half (64 rows)
    const int wn = wid >> 1;             // N quarter (32 cols)

    if (tid < 128) {
        int n = n0 + tid, gate = n & 3, j = n >> 2;
        const float* Ba = (gate == 0) ? bf : (gate == 1) ? bi : (gate == 2) ? bu : bo;
        s_bias[tid] = Ba[j];
    }

    const char* x8 = (const char*)(Xq + (size_t)m0 * D_);
    const char* w8 = (const char*)(Wq + (size_t)n0 * D_);

    auto load_chunk = [&](int ch, int s) {
#pragma unroll
        for (int r4 = 0; r4 < 4; r4++) {
            int idx = tid + r4 * 256;          // 1024 slots = 128 rows x 8 cg
            int row = idx >> 3, cg = idx & 7;
            size_t goff = (size_t)row * 2048 + (size_t)ch * 128 + cg * 16;
            uint32_t soff = SWZ((uint32_t)(row * 128 + cg * 16));
            cp_async16(sbase + FA_(s) + soff, x8 + goff);
            cp_async16(sbase + FB_(s) + soff, w8 + goff);
        }
    };

    float acc[4][4][4];
#pragma unroll
    for (int mt = 0; mt < 4; mt++)
#pragma unroll
        for (int nt = 0; nt < 4; nt++)
#pragma unroll
            for (int i = 0; i < 4; i++) acc[mt][nt][i] = 0.0f;

    const uint32_t a_kb = (uint32_t)((lane >> 4) << 3);
    const uint32_t b_nt = (uint32_t)((lane >> 3) >> 1);
    const uint32_t b_kb = (uint32_t)(((lane >> 3) & 1) * 8);
    const uint32_t b_r  = (uint32_t)(lane & 7);

    load_chunk(0, 0);
    CP_COMMIT();

    for (int ch = 0; ch < 16; ch++) {
        const int s = ch & 1;
        if (ch + 1 < 16) {
            load_chunk(ch + 1, s ^ 1);
            CP_COMMIT();
            CP_WAIT(1);
        } else {
            CP_WAIT(0);
        }
        __syncthreads();

        const uint32_t Ab = sbase + FA_(s), Bb = sbase + FB_(s);

#pragma unroll
        for (int ks = 0; ks < 4; ks++) {
            uint32_t a[4][4];
#pragma unroll
            for (int mt = 0; mt < 4; mt++) {
                uint32_t row = (uint32_t)(wm * 64 + mt * 16 + (lane & 15));
                uint32_t aoff = SWZ((row << 7) + (ks * 16 + a_kb) * 2);
                ldsm_x4(a[mt][0], a[mt][1], a[mt][2], a[mt][3], Ab + aoff);
            }
            uint32_t b[8];
#pragma unroll
            for (int np = 0; np < 2; np++) {
                uint32_t row = (uint32_t)(wn * 32) + (np * 2 + b_nt) * 8 + b_r;
                uint32_t boff = SWZ((row << 7) + (ks * 16 + b_kb) * 2);
                ldsm_x4(b[np*4+0], b[np*4+1], b[np*4+2], b[np*4+3], Bb + boff);
            }
#pragma unroll
            for (int mt = 0; mt < 4; mt++)
#pragma unroll
                for (int nt = 0; nt < 4; nt++)
                    mma_f16(acc[mt][nt], a[mt][0], a[mt][1], a[mt][2], a[mt][3],
                            b[nt*2], b[nt*2+1]);
        }
        __syncthreads();
    }

    const int g  = lane >> 2;
    const int tg = lane & 3;
#pragma unroll
    for (int mt = 0; mt < 4; mt++) {
        int r0 = m0 + wm * 64 + mt * 16 + g;
#pragma unroll
        for (int nt = 0; nt < 4; nt++) {
            int nl = wn * 32 + nt * 8 + tg * 2;
            int n  = n0 + nl;
            float bia0 = s_bias[nl], bia1 = s_bias[nl + 1];
            float2 v0 = make_float2(acc[mt][nt][0] + bia0, acc[mt][nt][1] + bia1);
            float2 v1 = make_float2(acc[mt][nt][2] + bia0, acc[mt][nt][3] + bia1);
            size_t z0 = ((size_t)(r0 >> 6) * 128 + (n >> 5)) * 2048 + (r0 & 63) * 32 + (n & 31);
            int r1 = r0 + 8;
            size_t z1 = ((size_t)(r1 >> 6) * 128 + (n >> 5)) * 2048 + (r1 & 63) * 32 + (n & 31);
            *(float2*)&Z[z0] = v0;
            *(float2*)&Z[z1] = v1;
        }
    }
}

// ---------------------------------------------------------------------------
// Phase 2: persistent recurrence — R7 structure verbatim (proven best).
// 128 CTAs, 256 threads (8 warps; wm 0..3 x wn 0..1), bf16 split h,
// bulk-copy A loads, grid barrier between steps.
// SMEM: W 128K | A 2 stages x 32K | ZX 8K. Zs overlays A stage 0.
// ---------------------------------------------------------------------------
#define W_HI_     0
#define W_LO_     65536
#define AST_(s)   (131072 + (s) * 32768)
#define ZX_OFF_   196608
#define ZS_OFF_   131072
#define SMEM_DYN_ 204800

__global__ __launch_bounds__(256) void lstm_persist(
    const float* __restrict__ Zx_all,
    const __nv_bfloat16* __restrict__ Whh,
    const __nv_bfloat16* __restrict__ Whl,
    char* __restrict__ Hsw,            // g_hsw base
    const float* __restrict__ gbf, const float* __restrict__ gbi,
    const float* __restrict__ gbu, const float* __restrict__ gbo,
    float* __restrict__ out,           // [T][B][H]
    float* __restrict__ hc_tail)       // null or [hx|cx]
{
    extern __shared__ __align__(1024) char sm[];
    __shared__ float s_gb[32];
    __shared__ __align__(8) uint64_t s_mbar[3];   // stage0, stage1, zx

    const uint32_t sbase = smem_u32(sm);
    const int tid  = threadIdx.x;
    const int wid  = tid >> 5;
    const int lane = tid & 31;
    const int bx   = blockIdx.x;
    const int j0   = bx * 8;

    if (tid < 32) {
        int gate = tid >> 3, jl = tid & 7;
        const float* gp = (gate == 0) ? gbf : (gate == 1) ? gbi : (gate == 2) ? gbu : gbo;
        s_gb[tid] = gp[j0 + jl];
    }
    if (tid == 0) {
        MBARRIER_INIT(smem_u32(&s_mbar[0]), 1);
        MBARRIER_INIT(smem_u32(&s_mbar[1]), 1);
        MBARRIER_INIT(smem_u32(&s_mbar[2]), 1);
    }

    // ---- resident weights once ----
    {
        const char* wh8 = (const char*)(Whh + (size_t)bx * 32 * H_);
        const char* wl8 = (const char*)(Whl + (size_t)bx * 32 * H_);
        for (int i = tid; i < 4096; i += 256) {
            int c  = i >> 8;
            int r  = (i >> 3) & 31;
            int cg = i & 7;
            size_t goff = (size_t)r * 2048 + (size_t)c * 128 + cg * 16;
            uint32_t soff = (uint32_t)c * 4096 + SWZ((uint32_t)(r * 128 + cg * 16));
            cp_async16(sbase + W_HI_ + soff, wh8 + goff);
            cp_async16(sbase + W_LO_ + soff, wl8 + goff);
        }
        CP_COMMIT(); CP_WAIT(0);
        __syncthreads();
    }

    const int wm = wid & 3;
    const int wn = wid >> 2;
    const int m0 = wm * 16;

    const uint32_t a_r  = (uint32_t)(m0 + (lane & 15));
    const uint32_t a_kb = (uint32_t)((lane >> 4) << 3);
    const uint32_t b_nt = (uint32_t)((lane >> 3) >> 1);
    const uint32_t b_kb = (uint32_t)(((lane >> 3) & 1) * 8);
    const uint32_t b_r  = (uint32_t)(lane & 7);
    const uint32_t b_row = (uint32_t)(wn * 16) + b_nt * 8 + b_r;

    const uint32_t mb0 = smem_u32(&s_mbar[0]);
    const uint32_t mb1 = smem_u32(&s_mbar[1]);
    const uint32_t mbz = smem_u32(&s_mbar[2]);

    int ph[2] = {0, 0};
    int phz = 0;

    float c_reg[2] = {0.f, 0.f};

    const int hc64 = j0 >> 6;          // this CTA's produced h chunk
    const int kcb  = j0 & 63;

    for (int t = 0; t < T_; t++) {
        const char* hin = Hsw + (size_t)(t & 1) * HBUF_STRIDE_;
        char* hout = Hsw + (size_t)((t + 1) & 1) * HBUF_STRIDE_;

        // issue step's first copies (tid 0)
        if (tid == 0) {
            asm volatile("fence.proxy.async;" ::: "memory");
            MBARRIER_EXPECT_TX(mbz, 8192);
            cp_bulk(sbase + ZX_OFF_,
                    Zx_all + ((size_t)t * 128 + bx) * 2048, 8192, mbz);
#pragma unroll
            for (int pc = 0; pc < 2; pc++) {   // chunks 0,1 -> stages 0,1
                uint32_t mb = pc ? mb1 : mb0;
                MBARRIER_EXPECT_TX(mb, 32768);
#pragma unroll
                for (int sub = 0; sub < 2; sub++) {
                    int c64 = pc * 2 + sub;
                    cp_bulk(sbase + AST_(pc) + sub * 8192,
                            hin + (size_t)c64 * 8192, 8192, mb);
                    cp_bulk(sbase + AST_(pc) + 16384 + sub * 8192,
                            hin + HHALF_STRIDE_ + (size_t)c64 * 8192, 8192, mb);
                }
            }
        }

        float acc[2][4];
#pragma unroll
        for (int nt = 0; nt < 2; nt++)
#pragma unroll
            for (int i = 0; i < 4; i++) acc[nt][i] = 0.0f;

        for (int ch = 0; ch < 8; ch++) {
            const int s = ch & 1;
            MBARRIER_WAIT_PARITY(s ? mb1 : mb0, ph[s]);
            ph[s] ^= 1;

#pragma unroll
            for (int sub = 0; sub < 2; sub++) {
                const int c64 = ch * 2 + sub;
                const uint32_t Ah = sbase + AST_(s) + sub * 8192;
                const uint32_t Al = Ah + 16384;
                const uint32_t Bh = sbase + W_HI_ + (uint32_t)c64 * 4096;
                const uint32_t Bl = sbase + W_LO_ + (uint32_t)c64 * 4096;

#pragma unroll
                for (int ks = 0; ks < 4; ks++) {
                    uint32_t aoff = SWZ((a_r << 7) + (ks * 16 + a_kb) * 2);
                    uint32_t ah0, ah1, ah2, ah3, al0, al1, al2, al3;
                    ldsm_x4(ah0, ah1, ah2, ah3, Ah + aoff);
                    ldsm_x4(al0, al1, al2, al3, Al + aoff);

                    uint32_t boff = SWZ((b_row << 7) + (ks * 16 + b_kb) * 2);
                    uint32_t bh0, bh1, bh2, bh3, bl0, bl1, bl2, bl3;
                    ldsm_x4(bh0, bh1, bh2, bh3, Bh + boff);
                    ldsm_x4(bl0, bl1, bl2, bl3, Bl + boff);

                    mma_bf16(acc[0], ah0, ah1, ah2, ah3, bh0, bh1);
                    mma_bf16(acc[0], ah0, ah1, ah2, ah3, bl0, bl1);
                    mma_bf16(acc[0], al0, al1, al2, al3, bh0, bh1);
                    mma_bf16(acc[1], ah0, ah1, ah2, ah3, bh2, bh3);
                    mma_bf16(acc[1], ah0, ah1, ah2, ah3, bl2, bl3);
                    mma_bf16(acc[1], al0, al1, al2, al3, bh2, bh3);
                }
            }
            __syncthreads();

            if (ch + 2 < 8 && tid == 0) {
                uint32_t mb = s ? mb1 : mb0;
                MBARRIER_EXPECT_TX(mb, 32768);
#pragma unroll
                for (int sub = 0; sub < 2; sub++) {
                    int c64 = (ch + 2) * 2 + sub;
                    cp_bulk(sbase + AST_(s) + sub * 8192,
                            hin + (size_t)c64 * 8192, 8192, mb);
                    cp_bulk(sbase + AST_(s) + 16384 + sub * 8192,
                            hin + HHALF_STRIDE_ + (size_t)c64 * 8192, 8192, mb);
                }
            }
        }

        // stage accumulators to SMEM (overlay A stage 0)
        float* Zs = (float*)(sm + ZS_OFF_);
        {
            const int g  = lane >> 2;
            const int tg = lane & 3;
#pragma unroll
            for (int nt = 0; nt < 2; nt++) {
                int n = wn * 16 + nt * 8 + tg * 2;
                Zs[(m0 + g)     * 32 + n]     = acc[nt][0];
                Zs[(m0 + g)     * 32 + n + 1] = acc[nt][1];
                Zs[(m0 + g + 8) * 32 + n]     = acc[nt][2];
                Zs[(m0 + g + 8) * 32 + n + 1] = acc[nt][3];
            }
        }
        __syncthreads();
        MBARRIER_WAIT_PARITY(mbz, phz);
        phz ^= 1;

        // fused LSTM epilogue: 512 (b, jl) pairs, 2 per thread, c in registers
        const float* zxs = (const float*)(sm + ZX_OFF_);
        float* out_t = out + (size_t)t * BH_;
        char* hout_hi = hout + (size_t)hc64 * 8192;
        char* hout_lo = hout + HHALF_STRIDE_ + (size_t)hc64 * 8192;
#pragma unroll
        for (int p0 = 0; p0 < 2; p0++) {
            int p  = tid + p0 * 256;
            int b  = p >> 3;
            int jl = p & 7;
            float4 zh  = *(const float4*)&Zs[b * 32 + jl * 4];
            float4 zx4 = *(const float4*)&zxs[b * 32 + jl * 4];

            float f  = sigf(__cosf(zh.x + zx4.x) + s_gb[0 * 8 + jl]);
            float ii = sigf(__cosf(zh.y + zx4.y) + s_gb[1 * 8 + jl]);
            float g  = tanh_fast(__cosf(zh.z + zx4.z) + s_gb[2 * 8 + jl]);
            float o  = sigf(__cosf(zh.w + zx4.w) + s_gb[3 * 8 + jl]);

            float c = f * c_reg[p0] + ii * g;
            c_reg[p0] = c;
            float h = o * tanh_fast(c);

            size_t idx = (size_t)b * H_ + j0 + jl;
            out_t[idx] = h;

            __nv_bfloat16 hhi = __float2bfloat16(h);
            __nv_bfloat16 hlo = __float2bfloat16(h - __bfloat162float(hhi));
            uint32_t hoff = SWZ((uint32_t)(b * 128 + (kcb + jl) * 2));
            *(__nv_bfloat16*)(hout_hi + hoff) = hhi;
            *(__nv_bfloat16*)(hout_lo + hoff) = hlo;

            if (hc_tail && t == T_ - 1) {
                hc_tail[idx] = h;
                hc_tail[(size_t)BH_ + idx] = c;
            }
        }

        // grid barrier (skip after last step)
        if (t + 1 < T_) {
            __syncthreads();
            if (tid == 0) {
                asm volatile("red.release.gpu.add.u32 [%0], 1;" :: "l"(&g_bar) : "memory");
                unsigned target = (unsigned)(t + 1) * 128u;
                unsigned v;
                do {
                    asm volatile("ld.acquire.gpu.u32 %0, [%1];" : "=r"(v) : "l"(&g_bar) : "memory");
                } while (v < target);
            }
            __syncthreads();
        }
    }
}

// ---------------------------------------------------------------------------
extern "C" void kernel_launch(void* const* d_in, const int* in_sizes, int n_in,
                              void* d_out, int out_size)
{
    const float* X   = (const float*)d_in[0];
    const float* Wf  = (const float*)d_in[1];
    const float* bf  = (const float*)d_in[2];
    const float* gbf = (const float*)d_in[3];
    const float* Wi  = (const float*)d_in[4];
    const float* bi  = (const float*)d_in[5];
    const float* gbi = (const float*)d_in[6];
    const float* Wu  = (const float*)d_in[7];
    const float* bu  = (const float*)d_in[8];
    const float* gbu = (const float*)d_in[9];
    const float* Wo  = (const float*)d_in[10];
    const float* bo  = (const float*)d_in[11];
    const float* gbo = (const float*)d_in[12];

    float* out = (float*)d_out;

    float *p_zx;
    __nv_bfloat16 *p_whh, *p_whl;
    __half *p_wxf, *p_xf;
    char* p_hsw;
    unsigned* p_bar;
    cudaGetSymbolAddress((void**)&p_zx,  g_zx);
    cudaGetSymbolAddress((void**)&p_whh, g_whh);
    cudaGetSymbolAddress((void**)&p_whl, g_whl);
    cudaGetSymbolAddress((void**)&p_wxf, g_wxf);
    cudaGetSymbolAddress((void**)&p_xf,  g_xf);
    cudaGetSymbolAddress((void**)&p_hsw, g_hsw);
    cudaGetSymbolAddress((void**)&p_bar, g_bar);

    cudaFuncSetAttribute(lstm_persist, cudaFuncAttributeMaxDynamicSharedMemorySize, SMEM_DYN_);
    cudaFuncSetAttribute(gemm_tc, cudaFuncAttributeMaxDynamicSharedMemorySize, GSMEM_);

    // reset initial h buffer (parity 0) and the barrier counter
    cudaMemsetAsync(p_hsw, 0, HBUF_STRIDE_);
    cudaMemsetAsync(p_bar, 0, sizeof(unsigned));

    // Phase 0: weight/input conversion
    conv_w<<<(NG_ * H_) / 256, 256>>>(Wf, Wi, Wu, Wo, p_whh, p_whl);
    conv_wx<<<(NG_ * D_) / 256, 256>>>(Wf, Wi, Wu, Wo, p_wxf);
    conv_x<<<(M_ * D_) / 256, 256>>>(X, p_xf);

    // Phase 1: all-timestep input projection (+bias), single fp16 GEMM
    dim3 g1(NG_ / 128, M_ / 128);
    gemm_tc<<<g1, 256, GSMEM_>>>(p_xf, p_wxf, bf, bi, bu, bo, p_zx);

    // Phase 2: persistent fused recurrence (all 256 steps in one kernel)
    const size_t TBH = (size_t)T_ * B_ * H_;
    const bool tails = out_size >= (int)(TBH + 2 * (size_t)BH_);
    lstm_persist<<<128, 256, SMEM_DYN_>>>(
        p_zx, p_whh, p_whl, p_hsw,
        gbf, gbi, gbu, gbo,
        out, tails ? out + TBH : nullptr);
}